// round 9
// baseline (speedup 1.0000x reference)
#include <cuda_runtime.h>
#include <cuda_bf16.h>
#include <math.h>

// ---------------------------------------------------------------------------
// Problem constants
// ---------------------------------------------------------------------------
#define BATCH 32
#define CCH   128           // channels / d_model
#define HH    110           // spatial
#define PIX   (HH*HH)       // 12100
#define KTOK  768
#define NHEAD 8
#define HD    16
#define NTOK  (BATCH*KTOK)  // 24576
#define YSTR  112           // padded row stride for y maps
#define CNT   128           // conv GEMM pixel tile
#define NPT   ((PIX + CNT - 1) / CNT)   // 95

typedef unsigned long long u64;

// ---------------------------------------------------------------------------
// helpers
// ---------------------------------------------------------------------------
__device__ __forceinline__ unsigned tf32_of(float x) {
    unsigned r; asm("cvt.rna.tf32.f32 %0, %1;" : "=r"(r) : "f"(x)); return r;
}
__device__ __forceinline__ float tf32f(float x) {
    return __uint_as_float(tf32_of(x));
}
__device__ __forceinline__ void split_tf32(float v, unsigned &hi, unsigned &lo) {
    hi = tf32_of(v);
    lo = tf32_of(v - __uint_as_float(hi));
}
__device__ __forceinline__ void mma_tf32(float* c, const unsigned* a, const unsigned* b) {
    asm("mma.sync.aligned.m16n8k8.row.col.f32.tf32.tf32.f32 "
        "{%0,%1,%2,%3},{%4,%5,%6,%7},{%8,%9},{%0,%1,%2,%3};"
        : "+f"(c[0]), "+f"(c[1]), "+f"(c[2]), "+f"(c[3])
        : "r"(a[0]), "r"(a[1]), "r"(a[2]), "r"(a[3]), "r"(b[0]), "r"(b[1]));
}

// ---------------------------------------------------------------------------
// Scratch (static device globals; no allocation allowed)
// ---------------------------------------------------------------------------
__device__ float g_yt[(size_t)BATCH*49*HH*YSTR];  // per-tap channel-reduced maps
__device__ float g_imp[BATCH*PIX];                // importance map
__device__ int   g_idx[BATCH*KTOK];               // selected pixel indices
__device__ float g_freq[64];                      // positional-encoding freqs
__device__ float g_tokens[NTOK*CCH];
__device__ float g_qkv[NTOK*3*CCH];
__device__ float g_attn[NTOK*CCH];
__device__ float g_t1[NTOK*CCH];
__device__ float g_h1[NTOK*2*CCH];
__device__ float g_t2[NTOK*CCH];

// ---------------------------------------------------------------------------
// 1a) conv as GEMM (3xTF32, fp32-accurate): Y[t][p] = sum_c W[t][c] X[c][p].
//     K-sliced A splits (49.5 KB smem -> 4 blocks/SM for latency hiding).
// ---------------------------------------------------------------------------
__global__ __launch_bounds__(256) void convgemm_kernel(
    const float* __restrict__ x, const float* __restrict__ w)
{
    extern __shared__ unsigned csm[];
    unsigned (*Ah)[33]  = (unsigned(*)[33])csm;                 // 64 x 33
    unsigned (*Al)[33]  = Ah + 64;
    unsigned (*Bh)[132] = (unsigned(*)[132])(csm + 2 * 64 * 33);// 32 x 132
    unsigned (*Bl)[132] = Bh + 32;

    const int pt = blockIdx.x, b = blockIdx.y;
    const int p0 = pt * CNT;
    const int tid = threadIdx.x, lane = tid & 31, wid = tid >> 5;
    const int wm = wid >> 2, wn = wid & 3;
    const int g = lane >> 2, tg = lane & 3;

    float acc[2][4][4];
#pragma unroll
    for (int mi = 0; mi < 2; mi++)
#pragma unroll
        for (int ni = 0; ni < 4; ni++)
#pragma unroll
            for (int e = 0; e < 4; e++) acc[mi][ni][e] = 0.f;

    for (int k0 = 0; k0 < 128; k0 += 32) {
        __syncthreads();
        // A slice: Ah/Al[t][ck] = split(w[(k0+ck)*49 + t]), rows 49..63 zero
        for (int e = tid; e < 64 * 32; e += 256) {
            const int t = e & 63, ck = e >> 6;
            const float v = (t < 49) ? w[(k0 + ck) * 49 + t] : 0.f;
            split_tf32(v, Ah[t][ck], Al[t][ck]);
        }
        // B slice
        for (int e = tid; e < 32 * 128; e += 256) {
            const int c = e >> 7, p = e & 127;
            const int gp = p0 + p;
            const float v = (gp < PIX) ? x[((size_t)b * CCH + k0 + c) * PIX + gp] : 0.f;
            split_tf32(v, Bh[c][p], Bl[c][p]);
        }
        __syncthreads();
#pragma unroll
        for (int ks = 0; ks < 4; ks++) {
            const int kb = ks * 8 + tg;
            unsigned ah[2][4], al[2][4];
#pragma unroll
            for (int mi = 0; mi < 2; mi++) {
                const int rr = wm * 32 + mi * 16 + g;
                ah[mi][0] = Ah[rr][kb];       al[mi][0] = Al[rr][kb];
                ah[mi][1] = Ah[rr + 8][kb];   al[mi][1] = Al[rr + 8][kb];
                ah[mi][2] = Ah[rr][kb + 4];   al[mi][2] = Al[rr][kb + 4];
                ah[mi][3] = Ah[rr + 8][kb+4]; al[mi][3] = Al[rr + 8][kb+4];
            }
#pragma unroll
            for (int ni = 0; ni < 4; ni++) {
                const int n0 = wn * 32 + ni * 8 + g;
                unsigned bh[2], bl[2];
                bh[0] = Bh[kb][n0];     bl[0] = Bl[kb][n0];
                bh[1] = Bh[kb + 4][n0]; bl[1] = Bl[kb + 4][n0];
#pragma unroll
                for (int mi = 0; mi < 2; mi++) {
                    mma_tf32(acc[mi][ni], ah[mi], bh);   // hi*hi
                    mma_tf32(acc[mi][ni], al[mi], bh);   // lo*hi
                    mma_tf32(acc[mi][ni], ah[mi], bl);   // hi*lo
                }
            }
        }
    }

#pragma unroll
    for (int mi = 0; mi < 2; mi++) {
        const int t = wm * 32 + mi * 16 + g;
#pragma unroll
        for (int ni = 0; ni < 4; ni++) {
            const int pcol = p0 + wn * 32 + ni * 8 + tg * 2;
            if (pcol < PIX) {
                const int r0r = pcol / HH, c0r = pcol - r0r * HH;
                const bool ok1 = (pcol + 1 < PIX);
                const int r1r = (pcol + 1) / HH, c1r = (pcol + 1) - r1r * HH;
                if (t < 49) {
                    float* yb = g_yt + ((size_t)b * 49 + t) * HH * YSTR;
                    yb[r0r * YSTR + c0r] = acc[mi][ni][0];
                    if (ok1) yb[r1r * YSTR + c1r] = acc[mi][ni][1];
                }
                if (t + 8 < 49) {
                    float* yb = g_yt + ((size_t)b * 49 + t + 8) * HH * YSTR;
                    yb[r0r * YSTR + c0r] = acc[mi][ni][2];
                    if (ok1) yb[r1r * YSTR + c1r] = acc[mi][ni][3];
                }
            }
        }
    }
}

// ---------------------------------------------------------------------------
// 1b) shift-add over 49 taps + BN + GELU + sigmoid, one thread per pixel.
// ---------------------------------------------------------------------------
__global__ void convadd_kernel(
    const float* __restrict__ cb, const float* __restrict__ bg,
    const float* __restrict__ bb, const float* __restrict__ bm,
    const float* __restrict__ bv)
{
    const int idx = blockIdx.x * 256 + threadIdx.x;
    if (idx >= BATCH * PIX) return;
    const int b = idx / PIX, p = idx - b * PIX;
    const int r = p / HH, c = p - r * HH;
    const float* yb = g_yt + (size_t)b * 49 * HH * YSTR;

    float a = 0.f;
#pragma unroll
    for (int u = 0; u < 7; u++) {
        const int sr = r + 5 * (u - 3);
        if (sr < 0 || sr >= HH) continue;
#pragma unroll
        for (int v = 0; v < 7; v++) {
            const int sc = c + 5 * (v - 3);
            if (sc >= 0 && sc < HH)
                a += yb[((u * 7 + v) * HH + sr) * YSTR + sc];
        }
    }

    const float scale = bg[0] * rsqrtf(bv[0] + 1e-5f);
    float y = a + cb[0];
    y = (y - bm[0]) * scale + bb[0];
    const float gl = 0.5f * y * (1.f + erff(y * 0.70710678118654752f));
    g_imp[idx] = 1.f / (1.f + expf(-gl));
}

// ---------------------------------------------------------------------------
// 3) top-K per batch: radix-256 threshold + ballot compaction, 1024 threads.
// ---------------------------------------------------------------------------
#define NCHK ((PIX + 255) / 256)   // 48
#define TKT  1024

__global__ __launch_bounds__(TKT) void topk_kernel()
{
    extern __shared__ unsigned sbits[];     // [PIX]
    __shared__ int hist[256];
    __shared__ int cgt[NCHK], ceq[NCHK];
    __shared__ unsigned sh_prefix;
    __shared__ int sh_above;

    const int b    = blockIdx.x;
    const int tid  = threadIdx.x;
    const int lane = tid & 31;
    const int wrp  = tid >> 5;              // 0..31
    const float* v = g_imp + b * PIX;

    for (int i = tid; i < PIX; i += TKT)
        sbits[i] = __float_as_uint(v[i]);
    __syncthreads();

    unsigned prefix = 0;
    int kneed = KTOK;

#pragma unroll
    for (int shift = 24; shift >= 0; shift -= 8) {
        if (tid < 256) hist[tid] = 0;
        __syncthreads();
        const unsigned pm = (shift == 24) ? 0u : (0xFFFFFFFFu << (shift + 8));
        for (int i = tid; i < PIX; i += TKT) {
            const unsigned bits = sbits[i];
            if ((bits & pm) == prefix)
                atomicAdd(&hist[(bits >> shift) & 255], 1);
        }
        __syncthreads();
        for (int off = 1; off < 256; off <<= 1) {
            int val = 0;
            if (tid < 256) val = (tid + off < 256) ? hist[tid + off] : 0;
            __syncthreads();
            if (tid < 256) hist[tid] += val;
            __syncthreads();
        }
        if (tid < 256) {
            const int here  = hist[tid];
            const int above = (tid == 255) ? 0 : hist[tid + 1];
            if (here >= kneed && above < kneed) {
                sh_prefix = prefix | ((unsigned)tid << shift);
                sh_above  = above;
            }
        }
        __syncthreads();
        prefix = sh_prefix;
        kneed -= sh_above;
        __syncthreads();
    }

    const unsigned T = prefix;
    const int tn = kneed;                    // ties to take (lowest index first)

    for (int c = wrp; c < NCHK; c += 32) {
        int gt = 0, eq = 0;
#pragma unroll
        for (int g = 0; g < 8; g++) {
            const int i = c * 256 + g * 32 + lane;
            const unsigned bits = (i < PIX) ? sbits[i] : 0u;
            const unsigned bg = __ballot_sync(0xffffffffu, bits > T);
            const unsigned be = __ballot_sync(0xffffffffu, bits == T && i < PIX);
            gt += __popc(bg); eq += __popc(be);
        }
        if (lane == 0) { cgt[c] = gt; ceq[c] = eq; }
    }
    __syncthreads();
    if (tid == 0) {
        int sg = 0, se = 0;
        for (int c = 0; c < NCHK; c++) {
            const int tg2 = cgt[c], te = ceq[c];
            cgt[c] = sg; ceq[c] = se;
            sg += tg2; se += te;
        }
    }
    __syncthreads();

    const unsigned lmask = (1u << lane) - 1u;
    for (int c = wrp; c < NCHK; c += 32) {
        int gt_run = cgt[c], eq_run = ceq[c];
#pragma unroll
        for (int g = 0; g < 8; g++) {
            const int i = c * 256 + g * 32 + lane;
            const unsigned bits = (i < PIX) ? sbits[i] : 0u;
            const bool isgt = bits > T;
            const bool iseq = (bits == T) && (i < PIX);
            const unsigned bg = __ballot_sync(0xffffffffu, isgt);
            const unsigned be = __ballot_sync(0xffffffffu, iseq);
            const int gt_before = gt_run + __popc(bg & lmask);
            const int eq_before = eq_run + __popc(be & lmask);
            if (isgt)
                g_idx[b * KTOK + gt_before + min(eq_before, tn)] = i;
            else if (iseq && eq_before < tn)
                g_idx[b * KTOK + gt_before + eq_before] = i;
            gt_run += __popc(bg);
            eq_run += __popc(be);
        }
    }
}

// ---------------------------------------------------------------------------
// 4) positional-encoding frequency table
// ---------------------------------------------------------------------------
__global__ void freq_kernel()
{
    const int i = threadIdx.x;           // 64
    const float cst = (float)(-(log(10000.0) / 128.0));
    const float a = (float)(2 * i) * cst;
    g_freq[i] = (float)exp((double)a);
}

// ---------------------------------------------------------------------------
// 5) gather tokens: tokens[b,k,c] = x[b,c,p]*imp[b,p] + PE[p,c]
// ---------------------------------------------------------------------------
__global__ void gather_kernel(const float* __restrict__ x)
{
    const int b = blockIdx.y, k = blockIdx.x, c = threadIdx.x;
    const int p = g_idx[b * KTOK + k];
    const float val = x[((size_t)b * CCH + c) * PIX + p] * g_imp[b * PIX + p];
    const float arg = (float)p * g_freq[c >> 1];
    const float pe  = (c & 1) ? cosf(arg) : sinf(arg);
    g_tokens[((size_t)b * KTOK + k) * CCH + c] = val + pe;
}

// ---------------------------------------------------------------------------
// 6) tf32 tensor-core GEMM: C[m,n] = act( sum_k A[m,k]*B[n,k] + bias[n] )
// ---------------------------------------------------------------------------
template <bool RELU>
__global__ __launch_bounds__(256) void gemm_tf32(
    const float* __restrict__ A, const float* __restrict__ B,
    const float* __restrict__ bias, float* __restrict__ C,
    int M, int N, int K)
{
    __shared__ unsigned As[128][33];
    __shared__ unsigned Bs[64][33];

    const int tid  = threadIdx.x;
    const int lane = tid & 31;
    const int wid  = tid >> 5;
    const int wm   = wid >> 1;
    const int wn   = wid & 1;
    const int g    = lane >> 2;
    const int tg   = lane & 3;
    const int bm   = blockIdx.y * 128, bn = blockIdx.x * 64;

    float acc[2][4][4];
#pragma unroll
    for (int mi = 0; mi < 2; mi++)
#pragma unroll
        for (int ni = 0; ni < 4; ni++)
#pragma unroll
            for (int e = 0; e < 4; e++) acc[mi][ni][e] = 0.f;

    for (int k0 = 0; k0 < K; k0 += 32) {
#pragma unroll
        for (int i = 0; i < 4; i++) {
            const int f = tid + i * 256;
            const int row = f >> 3, c4 = (f & 7) * 4;
            const float4 v = *(const float4*)&A[(size_t)(bm + row) * K + k0 + c4];
            As[row][c4 + 0] = tf32_of(v.x); As[row][c4 + 1] = tf32_of(v.y);
            As[row][c4 + 2] = tf32_of(v.z); As[row][c4 + 3] = tf32_of(v.w);
        }
#pragma unroll
        for (int i = 0; i < 2; i++) {
            const int f = tid + i * 256;
            const int row = f >> 3, c4 = (f & 7) * 4;
            const float4 v = *(const float4*)&B[(size_t)(bn + row) * K + k0 + c4];
            Bs[row][c4 + 0] = tf32_of(v.x); Bs[row][c4 + 1] = tf32_of(v.y);
            Bs[row][c4 + 2] = tf32_of(v.z); Bs[row][c4 + 3] = tf32_of(v.w);
        }
        __syncthreads();

#pragma unroll
        for (int ks = 0; ks < 4; ks++) {
            const int kb = ks * 8;
            unsigned a[2][4], bf[4][2];
#pragma unroll
            for (int mi = 0; mi < 2; mi++) {
                const int r0 = wm * 32 + mi * 16 + g;
                a[mi][0] = As[r0][kb + tg];
                a[mi][1] = As[r0 + 8][kb + tg];
                a[mi][2] = As[r0][kb + tg + 4];
                a[mi][3] = As[r0 + 8][kb + tg + 4];
            }
#pragma unroll
            for (int ni = 0; ni < 4; ni++) {
                const int n0 = wn * 32 + ni * 8 + g;
                bf[ni][0] = Bs[n0][kb + tg];
                bf[ni][1] = Bs[n0][kb + tg + 4];
            }
#pragma unroll
            for (int mi = 0; mi < 2; mi++)
#pragma unroll
                for (int ni = 0; ni < 4; ni++)
                    mma_tf32(acc[mi][ni], a[mi], bf[ni]);
        }
        __syncthreads();
    }

#pragma unroll
    for (int mi = 0; mi < 2; mi++) {
        const int r0 = bm + wm * 32 + mi * 16 + g;
#pragma unroll
        for (int ni = 0; ni < 4; ni++) {
            const int c0 = bn + wn * 32 + ni * 8 + tg * 2;
            const float b0 = bias[c0], b1 = bias[c0 + 1];
            float2 v0 = { acc[mi][ni][0] + b0, acc[mi][ni][1] + b1 };
            float2 v1 = { acc[mi][ni][2] + b0, acc[mi][ni][3] + b1 };
            if (RELU) {
                v0.x = fmaxf(v0.x, 0.f); v0.y = fmaxf(v0.y, 0.f);
                v1.x = fmaxf(v1.x, 0.f); v1.y = fmaxf(v1.y, 0.f);
            }
            *(float2*)&C[(size_t)r0 * N + c0]       = v0;
            *(float2*)&C[(size_t)(r0 + 8) * N + c0] = v1;
        }
    }
}

// ---------------------------------------------------------------------------
// 6b) fused GEMM + bias + residual + LayerNorm. BN = 128 = full d_model.
// ---------------------------------------------------------------------------
__global__ __launch_bounds__(256) void gemm_ln(
    const float* __restrict__ A, const float* __restrict__ B,
    const float* __restrict__ bias, const float* __restrict__ R,
    const float* __restrict__ gam, const float* __restrict__ bet,
    float* __restrict__ out, int K)
{
    __shared__ unsigned As[128][33];
    __shared__ unsigned Bs[128][33];
    __shared__ float2 part[2][128];

    const int tid  = threadIdx.x;
    const int lane = tid & 31;
    const int wid  = tid >> 5;
    const int wm   = wid >> 1;
    const int wn   = wid & 1;
    const int g    = lane >> 2;
    const int tg   = lane & 3;
    const int bm   = blockIdx.x * 128;

    float acc[2][8][4];
#pragma unroll
    for (int mi = 0; mi < 2; mi++)
#pragma unroll
        for (int ni = 0; ni < 8; ni++)
#pragma unroll
            for (int e = 0; e < 4; e++) acc[mi][ni][e] = 0.f;

    for (int k0 = 0; k0 < K; k0 += 32) {
#pragma unroll
        for (int i = 0; i < 4; i++) {
            const int f = tid + i * 256;
            const int row = f >> 3, c4 = (f & 7) * 4;
            const float4 va = *(const float4*)&A[(size_t)(bm + row) * K + k0 + c4];
            As[row][c4 + 0] = tf32_of(va.x); As[row][c4 + 1] = tf32_of(va.y);
            As[row][c4 + 2] = tf32_of(va.z); As[row][c4 + 3] = tf32_of(va.w);
            const float4 vb = *(const float4*)&B[(size_t)row * K + k0 + c4];
            Bs[row][c4 + 0] = tf32_of(vb.x); Bs[row][c4 + 1] = tf32_of(vb.y);
            Bs[row][c4 + 2] = tf32_of(vb.z); Bs[row][c4 + 3] = tf32_of(vb.w);
        }
        __syncthreads();

#pragma unroll
        for (int ks = 0; ks < 4; ks++) {
            const int kb = ks * 8;
            unsigned a[2][4], bf[8][2];
#pragma unroll
            for (int mi = 0; mi < 2; mi++) {
                const int r0 = wm * 32 + mi * 16 + g;
                a[mi][0] = As[r0][kb + tg];
                a[mi][1] = As[r0 + 8][kb + tg];
                a[mi][2] = As[r0][kb + tg + 4];
                a[mi][3] = As[r0 + 8][kb + tg + 4];
            }
#pragma unroll
            for (int ni = 0; ni < 8; ni++) {
                const int n0 = wn * 64 + ni * 8 + g;
                bf[ni][0] = Bs[n0][kb + tg];
                bf[ni][1] = Bs[n0][kb + tg + 4];
            }
#pragma unroll
            for (int mi = 0; mi < 2; mi++)
#pragma unroll
                for (int ni = 0; ni < 8; ni++)
                    mma_tf32(acc[mi][ni], a[mi], bf[ni]);
        }
        __syncthreads();
    }

    float v0s[2][8][2], v1s[2][8][2];
    float sum[2][2], sq[2][2];
#pragma unroll
    for (int mi = 0; mi < 2; mi++) {
        sum[mi][0] = sum[mi][1] = 0.f;
        sq[mi][0]  = sq[mi][1]  = 0.f;
        const int r0 = bm + wm * 32 + mi * 16 + g;
#pragma unroll
        for (int ni = 0; ni < 8; ni++) {
            const int c0 = wn * 64 + ni * 8 + tg * 2;
            const float b0 = bias[c0], b1 = bias[c0 + 1];
            const float2 ra = *(const float2*)&R[(size_t)r0 * CCH + c0];
            const float2 rb = *(const float2*)&R[(size_t)(r0 + 8) * CCH + c0];
            const float x0 = acc[mi][ni][0] + b0 + ra.x;
            const float x1 = acc[mi][ni][1] + b1 + ra.y;
            const float x2 = acc[mi][ni][2] + b0 + rb.x;
            const float x3 = acc[mi][ni][3] + b1 + rb.y;
            v0s[mi][ni][0] = x0; v0s[mi][ni][1] = x1;
            v1s[mi][ni][0] = x2; v1s[mi][ni][1] = x3;
            sum[mi][0] += x0 + x1;         sq[mi][0] += x0*x0 + x1*x1;
            sum[mi][1] += x2 + x3;         sq[mi][1] += x2*x2 + x3*x3;
        }
#pragma unroll
        for (int off = 1; off < 4; off <<= 1) {
            sum[mi][0] += __shfl_xor_sync(0xffffffffu, sum[mi][0], off);
            sq[mi][0]  += __shfl_xor_sync(0xffffffffu, sq[mi][0],  off);
            sum[mi][1] += __shfl_xor_sync(0xffffffffu, sum[mi][1], off);
            sq[mi][1]  += __shfl_xor_sync(0xffffffffu, sq[mi][1],  off);
        }
    }
    if (tg == 0) {
#pragma unroll
        for (int mi = 0; mi < 2; mi++) {
            const int rl = wm * 32 + mi * 16 + g;
            part[wn][rl]     = make_float2(sum[mi][0], sq[mi][0]);
            part[wn][rl + 8] = make_float2(sum[mi][1], sq[mi][1]);
        }
    }
    __syncthreads();

#pragma unroll
    for (int mi = 0; mi < 2; mi++) {
        const int rl = wm * 32 + mi * 16 + g;
#pragma unroll
        for (int half = 0; half < 2; half++) {
            const float2 p0 = part[0][rl + half * 8];
            const float2 p1 = part[1][rl + half * 8];
            const float mu  = (p0.x + p1.x) * (1.f / 128.f);
            const float var = (p0.y + p1.y) * (1.f / 128.f) - mu * mu;
            const float inv = rsqrtf(var + 1e-5f);
            const int row = bm + wm * 32 + mi * 16 + half * 8 + g;
#pragma unroll
            for (int ni = 0; ni < 8; ni++) {
                const int c0 = wn * 64 + ni * 8 + tg * 2;
                const float gv0 = gam[c0], gv1 = gam[c0 + 1];
                const float bv0 = bet[c0], bv1 = bet[c0 + 1];
                const float x0 = (half == 0) ? v0s[mi][ni][0] : v1s[mi][ni][0];
                const float x1 = (half == 0) ? v0s[mi][ni][1] : v1s[mi][ni][1];
                float2 o;
                o.x = (x0 - mu) * inv * gv0 + bv0;
                o.y = (x1 - mu) * inv * gv1 + bv1;
                *(float2*)&out[(size_t)row * CCH + c0] = o;
            }
        }
    }
}

// ---------------------------------------------------------------------------
// 7) tensor-core flash attention. grid (NHEAD, BATCH, 2), 256 threads.
// ---------------------------------------------------------------------------
__global__ __launch_bounds__(256) void attn_kernel()
{
    __shared__ unsigned sK[256][18];
    __shared__ unsigned sV[256][24];

    const int h = blockIdx.x, b = blockIdx.y, qh = blockIdx.z;
    const int tid  = threadIdx.x;
    const int lane = tid & 31;
    const int w    = tid >> 5;
    const int g    = lane >> 2;
    const int tg   = lane & 3;
    const float* qkv = g_qkv + (size_t)b * KTOK * 384;
    const int qbase = qh * 384 + w * 48;

    unsigned qa[3][8];
#pragma unroll
    for (int qt = 0; qt < 3; qt++) {
        const int row = qbase + qt * 16 + g;
        const float* q0 = qkv + (size_t)row * 384 + h * 16;
        const float* q8 = q0 + 8 * 384;
        qa[qt][0] = tf32_of(q0[tg]      * 0.25f);
        qa[qt][1] = tf32_of(q8[tg]      * 0.25f);
        qa[qt][2] = tf32_of(q0[tg + 4]  * 0.25f);
        qa[qt][3] = tf32_of(q8[tg + 4]  * 0.25f);
        qa[qt][4] = tf32_of(q0[tg + 8]  * 0.25f);
        qa[qt][5] = tf32_of(q8[tg + 8]  * 0.25f);
        qa[qt][6] = tf32_of(q0[tg + 12] * 0.25f);
        qa[qt][7] = tf32_of(q8[tg + 12] * 0.25f);
    }

    float m[3][2], l[3][2], o[3][2][4];
#pragma unroll
    for (int qt = 0; qt < 3; qt++) {
        m[qt][0] = m[qt][1] = -1e30f;
        l[qt][0] = l[qt][1] = 0.f;
#pragma unroll
        for (int n = 0; n < 2; n++)
#pragma unroll
            for (int e = 0; e < 4; e++) o[qt][n][e] = 0.f;
    }

    const int src0 = (lane & 28) | (tg >> 1);
    const int src2 = src0 + 2;

    for (int ch = 0; ch < 3; ch++) {
        __syncthreads();
        for (int e = tid; e < 256 * 16; e += 256) {
            const int j = e >> 4, d = e & 15;
            const size_t base = (size_t)(ch * 256 + j) * 384 + h * 16 + d;
            sK[j][d] = tf32_of(qkv[base + 128]);
            sV[j][d] = tf32_of(qkv[base + 256]);
        }
        __syncthreads();

        for (int sub = 0; sub < 8; sub++) {
            unsigned kb[4][2][2];
#pragma unroll
            for (int t = 0; t < 4; t++) {
                const int key = sub * 32 + t * 8 + g;
                kb[t][0][0] = sK[key][tg];
                kb[t][0][1] = sK[key][tg + 4];
                kb[t][1][0] = sK[key][tg + 8];
                kb[t][1][1] = sK[key][tg + 12];
            }
#pragma unroll
            for (int qt = 0; qt < 3; qt++) {
                float s[4][4];
#pragma unroll
                for (int t = 0; t < 4; t++) {
                    s[t][0] = s[t][1] = s[t][2] = s[t][3] = 0.f;
                    mma_tf32(s[t], qa[qt],     kb[t][0]);
                    mma_tf32(s[t], qa[qt] + 4, kb[t][1]);
                }
                float mx0 = s[0][0], mx1 = s[0][2];
#pragma unroll
                for (int t = 0; t < 4; t++) {
                    mx0 = fmaxf(mx0, fmaxf(s[t][0], s[t][1]));
                    mx1 = fmaxf(mx1, fmaxf(s[t][2], s[t][3]));
                }
                mx0 = fmaxf(mx0, __shfl_xor_sync(0xffffffffu, mx0, 1));
                mx0 = fmaxf(mx0, __shfl_xor_sync(0xffffffffu, mx0, 2));
                mx1 = fmaxf(mx1, __shfl_xor_sync(0xffffffffu, mx1, 1));
                mx1 = fmaxf(mx1, __shfl_xor_sync(0xffffffffu, mx1, 2));
                const float nm0 = fmaxf(m[qt][0], mx0);
                const float nm1 = fmaxf(m[qt][1], mx1);
                const float f0 = __expf(m[qt][0] - nm0);
                const float f1 = __expf(m[qt][1] - nm1);
                m[qt][0] = nm0; m[qt][1] = nm1;
                float s0 = 0.f, s1 = 0.f;
#pragma unroll
                for (int t = 0; t < 4; t++) {
                    s[t][0] = tf32f(__expf(s[t][0] - nm0));
                    s[t][1] = tf32f(__expf(s[t][1] - nm0));
                    s[t][2] = tf32f(__expf(s[t][2] - nm1));
                    s[t][3] = tf32f(__expf(s[t][3] - nm1));
                    s0 += s[t][0] + s[t][1];
                    s1 += s[t][2] + s[t][3];
                }
                l[qt][0] = l[qt][0] * f0 + s0;
                l[qt][1] = l[qt][1] * f1 + s1;
#pragma unroll
                for (int n = 0; n < 2; n++) {
                    o[qt][n][0] *= f0; o[qt][n][1] *= f0;
                    o[qt][n][2] *= f1; o[qt][n][3] *= f1;
                }
#pragma unroll
                for (int t = 0; t < 4; t++) {
                    unsigned a[4];
                    {
                        const float t00 = __shfl_sync(0xffffffffu, s[t][0], src0);
                        const float t01 = __shfl_sync(0xffffffffu, s[t][1], src0);
                        const float t10 = __shfl_sync(0xffffffffu, s[t][2], src0);
                        const float t11 = __shfl_sync(0xffffffffu, s[t][3], src0);
                        a[0] = __float_as_uint((tg & 1) ? t01 : t00);
                        a[1] = __float_as_uint((tg & 1) ? t11 : t10);
                        const float u00 = __shfl_sync(0xffffffffu, s[t][0], src2);
                        const float u01 = __shfl_sync(0xffffffffu, s[t][1], src2);
                        const float u10 = __shfl_sync(0xffffffffu, s[t][2], src2);
                        const float u11 = __shfl_sync(0xffffffffu, s[t][3], src2);
                        a[2] = __float_as_uint((tg & 1) ? u01 : u00);
                        a[3] = __float_as_uint((tg & 1) ? u11 : u10);
                    }
                    const int key = sub * 32 + t * 8;
                    unsigned vb0[2], vb1[2];
                    vb0[0] = sV[key + tg][g];         vb0[1] = sV[key + tg + 4][g];
                    vb1[0] = sV[key + tg][g + 8];     vb1[1] = sV[key + tg + 4][g + 8];
                    mma_tf32(o[qt][0], a, vb0);
                    mma_tf32(o[qt][1], a, vb1);
                }
            }
        }
    }

#pragma unroll
    for (int qt = 0; qt < 3; qt++) {
        float l0 = l[qt][0], l1 = l[qt][1];
        l0 += __shfl_xor_sync(0xffffffffu, l0, 1);
        l0 += __shfl_xor_sync(0xffffffffu, l0, 2);
        l1 += __shfl_xor_sync(0xffffffffu, l1, 1);
        l1 += __shfl_xor_sync(0xffffffffu, l1, 2);
        const float inv0 = 1.f / l0, inv1 = 1.f / l1;
        const int row = qbase + qt * 16 + g;
        float* out0 = g_attn + ((size_t)b * KTOK + row) * CCH + h * 16 + tg * 2;
        float* out8 = out0 + 8 * CCH;
#pragma unroll
        for (int n = 0; n < 2; n++) {
            *(float2*)(out0 + n * 8) = make_float2(o[qt][n][0] * inv0, o[qt][n][1] * inv0);
            *(float2*)(out8 + n * 8) = make_float2(o[qt][n][2] * inv1, o[qt][n][3] * inv1);
        }
    }
}

// ---------------------------------------------------------------------------
// 9) out = x * imp (everywhere); token scatter overwrites selected pixels.
// ---------------------------------------------------------------------------
__global__ void xs_kernel(const float* __restrict__ x, float* __restrict__ out)
{
    const unsigned i = blockIdx.x * 256u + threadIdx.x;
    const unsigned total = (unsigned)BATCH * CCH * (PIX / 4);
    if (i >= total) return;
    const unsigned base = i * 4u;
    const unsigned p4 = base % PIX;
    const unsigned b  = (base / PIX) / CCH;
    const float4 xv = *(const float4*)(x + base);
    const float* ip = g_imp + (size_t)b * PIX + p4;
    float4 o;
    o.x = xv.x * ip[0]; o.y = xv.y * ip[1]; o.z = xv.z * ip[2]; o.w = xv.w * ip[3];
    *(float4*)(out + base) = o;
}

__global__ void scatter_kernel(float* __restrict__ out)
{
    const int b = blockIdx.y, k = blockIdx.x, c = threadIdx.x;
    const int p = g_idx[b * KTOK + k];
    out[((size_t)b * CCH + c) * PIX + p] = g_t2[((size_t)b * KTOK + k) * CCH + c];
}

// ---------------------------------------------------------------------------
// launch — fork-join: xs (x*imp, 396 MB streamed) runs on cudaStreamPerThread
// overlapped with the token/transformer chain on the legacy stream.
// ---------------------------------------------------------------------------
extern "C" void kernel_launch(void* const* d_in, const int* in_sizes, int n_in,
                              void* d_out, int out_size)
{
    const float* x      = (const float*)d_in[0];
    const float* conv_w = (const float*)d_in[1];
    const float* conv_b = (const float*)d_in[2];
    const float* bn_g   = (const float*)d_in[3];
    const float* bn_b   = (const float*)d_in[4];
    const float* bn_m   = (const float*)d_in[5];
    const float* bn_v   = (const float*)d_in[6];
    const float* w_qkv  = (const float*)d_in[7];
    const float* b_qkv  = (const float*)d_in[8];
    const float* w_o    = (const float*)d_in[9];
    const float* b_o    = (const float*)d_in[10];
    const float* ln1_g  = (const float*)d_in[11];
    const float* ln1_b  = (const float*)d_in[12];
    const float* w1     = (const float*)d_in[13];
    const float* b1     = (const float*)d_in[14];
    const float* w2     = (const float*)d_in[15];
    const float* b2     = (const float*)d_in[16];
    const float* ln2_g  = (const float*)d_in[17];
    const float* ln2_b  = (const float*)d_in[18];
    float* out = (float*)d_out;

    float *p_tokens, *p_qkv, *p_attn, *p_t1, *p_h1, *p_t2;
    cudaGetSymbolAddress((void**)&p_tokens, g_tokens);
    cudaGetSymbolAddress((void**)&p_qkv,    g_qkv);
    cudaGetSymbolAddress((void**)&p_attn,   g_attn);
    cudaGetSymbolAddress((void**)&p_t1,     g_t1);
    cudaGetSymbolAddress((void**)&p_h1,     g_h1);
    cudaGetSymbolAddress((void**)&p_t2,     g_t2);

    const int convgemm_smem = (2 * 64 * 33 + 2 * 32 * 132) * (int)sizeof(unsigned);
    cudaFuncSetAttribute(convgemm_kernel, cudaFuncAttributeMaxDynamicSharedMemorySize,
                         convgemm_smem);
    cudaFuncSetAttribute(topk_kernel, cudaFuncAttributeMaxDynamicSharedMemorySize,
                         PIX * (int)sizeof(unsigned));

    // events for fork/join (host objects only; intentionally not destroyed —
    // destroying objects referenced by an in-progress capture is UB)
    cudaEvent_t e_fork, e_join;
    cudaEventCreateWithFlags(&e_fork, cudaEventDisableTiming);
    cudaEventCreateWithFlags(&e_join, cudaEventDisableTiming);

    // conv -> importance
    freq_kernel<<<1, 64>>>();
    convgemm_kernel<<<dim3(NPT, BATCH), 256, convgemm_smem>>>(x, conv_w);
    convadd_kernel<<<(BATCH * PIX + 255) / 256, 256>>>(conv_b, bn_g, bn_b, bn_m, bn_v);

    // fork: xs pass depends only on imp — run it on the side stream
    cudaEventRecord(e_fork, 0);
    cudaStreamWaitEvent(cudaStreamPerThread, e_fork, 0);
    xs_kernel<<<(BATCH * CCH * (PIX / 4) + 255) / 256, 256, 0, cudaStreamPerThread>>>(x, out);
    cudaEventRecord(e_join, cudaStreamPerThread);

    // main chain: top-K -> tokens -> transformer
    topk_kernel<<<BATCH, TKT, PIX * sizeof(unsigned)>>>();
    gather_kernel<<<dim3(KTOK, BATCH), CCH>>>(x);
    gemm_tf32<false><<<dim3(384 / 64, NTOK / 128), 256>>>(p_tokens, w_qkv, b_qkv, p_qkv, NTOK, 384, 128);
    attn_kernel<<<dim3(NHEAD, BATCH, 2), 256>>>();
    gemm_ln<<<NTOK / 128, 256>>>(p_attn, w_o, b_o, p_tokens, ln1_g, ln1_b, p_t1, 128);
    gemm_tf32<true ><<<dim3(256 / 64, NTOK / 128), 256>>>(p_t1, w1, b1, p_h1, NTOK, 256, 128);
    gemm_ln<<<NTOK / 128, 256>>>(p_h1, w2, b2, p_t1, ln2_g, ln2_b, p_t2, 256);

    // join, then scatter transformed tokens over the xs output
    cudaStreamWaitEvent(0, e_join, 0);
    scatter_kernel<<<dim3(KTOK, BATCH), CCH>>>(out);
}

// round 10
// speedup vs baseline: 1.0236x; 1.0236x over previous
#include <cuda_runtime.h>
#include <cuda_bf16.h>
#include <math.h>

// ---------------------------------------------------------------------------
// Problem constants
// ---------------------------------------------------------------------------
#define BATCH 32
#define CCH   128           // channels / d_model
#define HH    110           // spatial
#define PIX   (HH*HH)       // 12100
#define KTOK  768
#define NHEAD 8
#define HD    16
#define NTOK  (BATCH*KTOK)  // 24576
#define YSTR  112           // padded row stride for y maps
#define CNT   128           // conv GEMM pixel tile
#define NPT   ((PIX + CNT - 1) / CNT)   // 95

typedef unsigned long long u64;

// ---------------------------------------------------------------------------
// helpers
// ---------------------------------------------------------------------------
__device__ __forceinline__ unsigned tf32_of(float x) {
    unsigned r; asm("cvt.rna.tf32.f32 %0, %1;" : "=r"(r) : "f"(x)); return r;
}
__device__ __forceinline__ float tf32f(float x) {
    return __uint_as_float(tf32_of(x));
}
__device__ __forceinline__ void split_tf32(float v, unsigned &hi, unsigned &lo) {
    hi = tf32_of(v);
    lo = tf32_of(v - __uint_as_float(hi));
}
__device__ __forceinline__ void mma_tf32(float* c, const unsigned* a, const unsigned* b) {
    asm("mma.sync.aligned.m16n8k8.row.col.f32.tf32.tf32.f32 "
        "{%0,%1,%2,%3},{%4,%5,%6,%7},{%8,%9},{%0,%1,%2,%3};"
        : "+f"(c[0]), "+f"(c[1]), "+f"(c[2]), "+f"(c[3])
        : "r"(a[0]), "r"(a[1]), "r"(a[2]), "r"(a[3]), "r"(b[0]), "r"(b[1]));
}

// ---------------------------------------------------------------------------
// Scratch (static device globals; no allocation allowed)
// ---------------------------------------------------------------------------
__device__ float g_yt[(size_t)BATCH*49*HH*YSTR];  // per-tap channel-reduced maps
__device__ float g_xt[(size_t)BATCH*PIX*CCH];     // pixel-major x copy [b][p][c]
__device__ float g_imp[BATCH*PIX];                // importance map
__device__ int   g_idx[BATCH*KTOK];               // selected pixel indices
__device__ int   g_inv[BATCH*PIX];                // pixel -> token slot (or -1)
__device__ float g_freq[64];                      // positional-encoding freqs
__device__ float g_tokens[NTOK*CCH];
__device__ float g_qkv[NTOK*3*CCH];
__device__ float g_attn[NTOK*CCH];
__device__ float g_t1[NTOK*CCH];
__device__ float g_h1[NTOK*2*CCH];
__device__ float g_t2[NTOK*CCH];

// ---------------------------------------------------------------------------
// 1a) conv as GEMM (3xTF32, fp32-accurate): Y[t][p] = sum_c W[t][c] X[c][p].
//     K-sliced A splits (49.5 KB smem -> higher occupancy). Also emits the
//     pixel-major transposed copy xt[b][p][c] (coalesced) for token gather.
// ---------------------------------------------------------------------------
__global__ __launch_bounds__(256) void convgemm_kernel(
    const float* __restrict__ x, const float* __restrict__ w)
{
    extern __shared__ unsigned csm[];
    unsigned (*Ah)[33]  = (unsigned(*)[33])csm;                 // 64 x 33
    unsigned (*Al)[33]  = Ah + 64;
    unsigned (*Bh)[132] = (unsigned(*)[132])(csm + 2 * 64 * 33);// 32 x 132
    unsigned (*Bl)[132] = Bh + 32;

    const int pt = blockIdx.x, b = blockIdx.y;
    const int p0 = pt * CNT;
    const int tid = threadIdx.x, lane = tid & 31, wid = tid >> 5;
    const int wm = wid >> 2, wn = wid & 3;
    const int g = lane >> 2, tg = lane & 3;

    float acc[2][4][4];
#pragma unroll
    for (int mi = 0; mi < 2; mi++)
#pragma unroll
        for (int ni = 0; ni < 4; ni++)
#pragma unroll
            for (int e = 0; e < 4; e++) acc[mi][ni][e] = 0.f;

    for (int k0 = 0; k0 < 128; k0 += 32) {
        __syncthreads();
        // A slice: Ah/Al[t][ck] = split(w[(k0+ck)*49 + t]), rows 49..63 zero
        for (int e = tid; e < 64 * 32; e += 256) {
            const int t = e & 63, ck = e >> 6;
            const float v = (t < 49) ? w[(k0 + ck) * 49 + t] : 0.f;
            split_tf32(v, Ah[t][ck], Al[t][ck]);
        }
        // B slice
        for (int e = tid; e < 32 * 128; e += 256) {
            const int c = e >> 7, p = e & 127;
            const int gp = p0 + p;
            const float v = (gp < PIX) ? x[((size_t)b * CCH + k0 + c) * PIX + gp] : 0.f;
            split_tf32(v, Bh[c][p], Bl[c][p]);
        }
        __syncthreads();

        // transposed write-back: xt[b][p][k0+c]  (warp = 32 contiguous c)
        for (int e = tid; e < 32 * 128; e += 256) {
            const int p = e >> 5, c = e & 31;
            const int gp = p0 + p;
            if (gp < PIX) {
                const float v = __uint_as_float(Bh[c][p]) + __uint_as_float(Bl[c][p]);
                g_xt[((size_t)b * PIX + gp) * CCH + k0 + c] = v;
            }
        }

#pragma unroll
        for (int ks = 0; ks < 4; ks++) {
            const int kb = ks * 8 + tg;
            unsigned ah[2][4], al[2][4];
#pragma unroll
            for (int mi = 0; mi < 2; mi++) {
                const int rr = wm * 32 + mi * 16 + g;
                ah[mi][0] = Ah[rr][kb];       al[mi][0] = Al[rr][kb];
                ah[mi][1] = Ah[rr + 8][kb];   al[mi][1] = Al[rr + 8][kb];
                ah[mi][2] = Ah[rr][kb + 4];   al[mi][2] = Al[rr][kb + 4];
                ah[mi][3] = Ah[rr + 8][kb+4]; al[mi][3] = Al[rr + 8][kb+4];
            }
#pragma unroll
            for (int ni = 0; ni < 4; ni++) {
                const int n0 = wn * 32 + ni * 8 + g;
                unsigned bh[2], bl[2];
                bh[0] = Bh[kb][n0];     bl[0] = Bl[kb][n0];
                bh[1] = Bh[kb + 4][n0]; bl[1] = Bl[kb + 4][n0];
#pragma unroll
                for (int mi = 0; mi < 2; mi++) {
                    mma_tf32(acc[mi][ni], ah[mi], bh);   // hi*hi
                    mma_tf32(acc[mi][ni], al[mi], bh);   // lo*hi
                    mma_tf32(acc[mi][ni], ah[mi], bl);   // hi*lo
                }
            }
        }
    }

#pragma unroll
    for (int mi = 0; mi < 2; mi++) {
        const int t = wm * 32 + mi * 16 + g;
#pragma unroll
        for (int ni = 0; ni < 4; ni++) {
            const int pcol = p0 + wn * 32 + ni * 8 + tg * 2;
            if (pcol < PIX) {
                const int r0r = pcol / HH, c0r = pcol - r0r * HH;
                const bool ok1 = (pcol + 1 < PIX);
                const int r1r = (pcol + 1) / HH, c1r = (pcol + 1) - r1r * HH;
                if (t < 49) {
                    float* yb = g_yt + ((size_t)b * 49 + t) * HH * YSTR;
                    yb[r0r * YSTR + c0r] = acc[mi][ni][0];
                    if (ok1) yb[r1r * YSTR + c1r] = acc[mi][ni][1];
                }
                if (t + 8 < 49) {
                    float* yb = g_yt + ((size_t)b * 49 + t + 8) * HH * YSTR;
                    yb[r0r * YSTR + c0r] = acc[mi][ni][2];
                    if (ok1) yb[r1r * YSTR + c1r] = acc[mi][ni][3];
                }
            }
        }
    }
}

// ---------------------------------------------------------------------------
// 1b) shift-add over 49 taps + BN + GELU + sigmoid, one thread per pixel.
// ---------------------------------------------------------------------------
__global__ void convadd_kernel(
    const float* __restrict__ cb, const float* __restrict__ bg,
    const float* __restrict__ bb, const float* __restrict__ bm,
    const float* __restrict__ bv)
{
    const int idx = blockIdx.x * 256 + threadIdx.x;
    if (idx >= BATCH * PIX) return;
    const int b = idx / PIX, p = idx - b * PIX;
    const int r = p / HH, c = p - r * HH;
    const float* yb = g_yt + (size_t)b * 49 * HH * YSTR;

    float a = 0.f;
#pragma unroll
    for (int u = 0; u < 7; u++) {
        const int sr = r + 5 * (u - 3);
        if (sr < 0 || sr >= HH) continue;
#pragma unroll
        for (int v = 0; v < 7; v++) {
            const int sc = c + 5 * (v - 3);
            if (sc >= 0 && sc < HH)
                a += yb[((u * 7 + v) * HH + sr) * YSTR + sc];
        }
    }

    const float scale = bg[0] * rsqrtf(bv[0] + 1e-5f);
    float y = a + cb[0];
    y = (y - bm[0]) * scale + bb[0];
    const float gl = 0.5f * y * (1.f + erff(y * 0.70710678118654752f));
    g_imp[idx] = 1.f / (1.f + expf(-gl));
}

// ---------------------------------------------------------------------------
// 3) top-K per batch: radix-256 threshold + ballot compaction. Fills g_inv.
// ---------------------------------------------------------------------------
#define NCHK ((PIX + 255) / 256)   // 48
#define TKT  1024

__global__ __launch_bounds__(TKT) void topk_kernel()
{
    extern __shared__ unsigned sbits[];     // [PIX]
    __shared__ int hist[256];
    __shared__ int cgt[NCHK], ceq[NCHK];
    __shared__ unsigned sh_prefix;
    __shared__ int sh_above;

    const int b    = blockIdx.x;
    const int tid  = threadIdx.x;
    const int lane = tid & 31;
    const int wrp  = tid >> 5;              // 0..31
    const float* v = g_imp + b * PIX;

    for (int i = tid; i < PIX; i += TKT) {
        sbits[i] = __float_as_uint(v[i]);
        g_inv[b * PIX + i] = -1;
    }
    __syncthreads();

    unsigned prefix = 0;
    int kneed = KTOK;

#pragma unroll
    for (int shift = 24; shift >= 0; shift -= 8) {
        if (tid < 256) hist[tid] = 0;
        __syncthreads();
        const unsigned pm = (shift == 24) ? 0u : (0xFFFFFFFFu << (shift + 8));
        for (int i = tid; i < PIX; i += TKT) {
            const unsigned bits = sbits[i];
            if ((bits & pm) == prefix)
                atomicAdd(&hist[(bits >> shift) & 255], 1);
        }
        __syncthreads();
        for (int off = 1; off < 256; off <<= 1) {
            int val = 0;
            if (tid < 256) val = (tid + off < 256) ? hist[tid + off] : 0;
            __syncthreads();
            if (tid < 256) hist[tid] += val;
            __syncthreads();
        }
        if (tid < 256) {
            const int here  = hist[tid];
            const int above = (tid == 255) ? 0 : hist[tid + 1];
            if (here >= kneed && above < kneed) {
                sh_prefix = prefix | ((unsigned)tid << shift);
                sh_above  = above;
            }
        }
        __syncthreads();
        prefix = sh_prefix;
        kneed -= sh_above;
        __syncthreads();
    }

    const unsigned T = prefix;
    const int tn = kneed;                    // ties to take (lowest index first)

    for (int c = wrp; c < NCHK; c += 32) {
        int gt = 0, eq = 0;
#pragma unroll
        for (int g = 0; g < 8; g++) {
            const int i = c * 256 + g * 32 + lane;
            const unsigned bits = (i < PIX) ? sbits[i] : 0u;
            const unsigned bg = __ballot_sync(0xffffffffu, bits > T);
            const unsigned be = __ballot_sync(0xffffffffu, bits == T && i < PIX);
            gt += __popc(bg); eq += __popc(be);
        }
        if (lane == 0) { cgt[c] = gt; ceq[c] = eq; }
    }
    __syncthreads();
    if (tid == 0) {
        int sg = 0, se = 0;
        for (int c = 0; c < NCHK; c++) {
            const int tg2 = cgt[c], te = ceq[c];
            cgt[c] = sg; ceq[c] = se;
            sg += tg2; se += te;
        }
    }
    __syncthreads();

    const unsigned lmask = (1u << lane) - 1u;
    for (int c = wrp; c < NCHK; c += 32) {
        int gt_run = cgt[c], eq_run = ceq[c];
#pragma unroll
        for (int g = 0; g < 8; g++) {
            const int i = c * 256 + g * 32 + lane;
            const unsigned bits = (i < PIX) ? sbits[i] : 0u;
            const bool isgt = bits > T;
            const bool iseq = (bits == T) && (i < PIX);
            const unsigned bg = __ballot_sync(0xffffffffu, isgt);
            const unsigned be = __ballot_sync(0xffffffffu, iseq);
            const int gt_before = gt_run + __popc(bg & lmask);
            const int eq_before = eq_run + __popc(be & lmask);
            int slot = -1;
            if (isgt)                         slot = gt_before + min(eq_before, tn);
            else if (iseq && eq_before < tn)  slot = gt_before + eq_before;
            if (slot >= 0) {
                g_idx[b * KTOK + slot] = i;
                g_inv[b * PIX + i] = slot;
            }
            gt_run += __popc(bg);
            eq_run += __popc(be);
        }
    }
}

// ---------------------------------------------------------------------------
// 4) positional-encoding frequency table
// ---------------------------------------------------------------------------
__global__ void freq_kernel()
{
    const int i = threadIdx.x;           // 64
    const float cst = (float)(-(log(10000.0) / 128.0));
    const float a = (float)(2 * i) * cst;
    g_freq[i] = (float)exp((double)a);
}

// ---------------------------------------------------------------------------
// 5) gather tokens from the pixel-major copy (coalesced 512 B rows):
//    tokens[b,k,c] = xt[b,p,c]*imp[b,p] + PE[p,c]
// ---------------------------------------------------------------------------
__global__ void gather_kernel()
{
    const int b = blockIdx.y;
    const int k = blockIdx.x * 2 + (threadIdx.x >> 7);
    const int c = threadIdx.x & 127;
    const int p = g_idx[b * KTOK + k];
    const float val = g_xt[((size_t)b * PIX + p) * CCH + c] * g_imp[b * PIX + p];
    const float arg = (float)p * g_freq[c >> 1];
    const float pe  = (c & 1) ? cosf(arg) : sinf(arg);
    g_tokens[((size_t)b * KTOK + k) * CCH + c] = val + pe;
}

// ---------------------------------------------------------------------------
// 6) tf32 tensor-core GEMM: C[m,n] = act( sum_k A[m,k]*B[n,k] + bias[n] )
// ---------------------------------------------------------------------------
template <bool RELU>
__global__ __launch_bounds__(256) void gemm_tf32(
    const float* __restrict__ A, const float* __restrict__ B,
    const float* __restrict__ bias, float* __restrict__ C,
    int M, int N, int K)
{
    __shared__ unsigned As[128][33];
    __shared__ unsigned Bs[64][33];

    const int tid  = threadIdx.x;
    const int lane = tid & 31;
    const int wid  = tid >> 5;
    const int wm   = wid >> 1;
    const int wn   = wid & 1;
    const int g    = lane >> 2;
    const int tg   = lane & 3;
    const int bm   = blockIdx.y * 128, bn = blockIdx.x * 64;

    float acc[2][4][4];
#pragma unroll
    for (int mi = 0; mi < 2; mi++)
#pragma unroll
        for (int ni = 0; ni < 4; ni++)
#pragma unroll
            for (int e = 0; e < 4; e++) acc[mi][ni][e] = 0.f;

    for (int k0 = 0; k0 < K; k0 += 32) {
#pragma unroll
        for (int i = 0; i < 4; i++) {
            const int f = tid + i * 256;
            const int row = f >> 3, c4 = (f & 7) * 4;
            const float4 v = *(const float4*)&A[(size_t)(bm + row) * K + k0 + c4];
            As[row][c4 + 0] = tf32_of(v.x); As[row][c4 + 1] = tf32_of(v.y);
            As[row][c4 + 2] = tf32_of(v.z); As[row][c4 + 3] = tf32_of(v.w);
        }
#pragma unroll
        for (int i = 0; i < 2; i++) {
            const int f = tid + i * 256;
            const int row = f >> 3, c4 = (f & 7) * 4;
            const float4 v = *(const float4*)&B[(size_t)(bn + row) * K + k0 + c4];
            Bs[row][c4 + 0] = tf32_of(v.x); Bs[row][c4 + 1] = tf32_of(v.y);
            Bs[row][c4 + 2] = tf32_of(v.z); Bs[row][c4 + 3] = tf32_of(v.w);
        }
        __syncthreads();

#pragma unroll
        for (int ks = 0; ks < 4; ks++) {
            const int kb = ks * 8;
            unsigned a[2][4], bf[4][2];
#pragma unroll
            for (int mi = 0; mi < 2; mi++) {
                const int r0 = wm * 32 + mi * 16 + g;
                a[mi][0] = As[r0][kb + tg];
                a[mi][1] = As[r0 + 8][kb + tg];
                a[mi][2] = As[r0][kb + tg + 4];
                a[mi][3] = As[r0 + 8][kb + tg + 4];
            }
#pragma unroll
            for (int ni = 0; ni < 4; ni++) {
                const int n0 = wn * 32 + ni * 8 + g;
                bf[ni][0] = Bs[n0][kb + tg];
                bf[ni][1] = Bs[n0][kb + tg + 4];
            }
#pragma unroll
            for (int mi = 0; mi < 2; mi++)
#pragma unroll
                for (int ni = 0; ni < 4; ni++)
                    mma_tf32(acc[mi][ni], a[mi], bf[ni]);
        }
        __syncthreads();
    }

#pragma unroll
    for (int mi = 0; mi < 2; mi++) {
        const int r0 = bm + wm * 32 + mi * 16 + g;
#pragma unroll
        for (int ni = 0; ni < 4; ni++) {
            const int c0 = bn + wn * 32 + ni * 8 + tg * 2;
            const float b0 = bias[c0], b1 = bias[c0 + 1];
            float2 v0 = { acc[mi][ni][0] + b0, acc[mi][ni][1] + b1 };
            float2 v1 = { acc[mi][ni][2] + b0, acc[mi][ni][3] + b1 };
            if (RELU) {
                v0.x = fmaxf(v0.x, 0.f); v0.y = fmaxf(v0.y, 0.f);
                v1.x = fmaxf(v1.x, 0.f); v1.y = fmaxf(v1.y, 0.f);
            }
            *(float2*)&C[(size_t)r0 * N + c0]       = v0;
            *(float2*)&C[(size_t)(r0 + 8) * N + c0] = v1;
        }
    }
}

// ---------------------------------------------------------------------------
// 6b) fused GEMM + bias + residual + LayerNorm. BN = 128 = full d_model.
// ---------------------------------------------------------------------------
__global__ __launch_bounds__(256) void gemm_ln(
    const float* __restrict__ A, const float* __restrict__ B,
    const float* __restrict__ bias, const float* __restrict__ R,
    const float* __restrict__ gam, const float* __restrict__ bet,
    float* __restrict__ out, int K)
{
    __shared__ unsigned As[128][33];
    __shared__ unsigned Bs[128][33];
    __shared__ float2 part[2][128];

    const int tid  = threadIdx.x;
    const int lane = tid & 31;
    const int wid  = tid >> 5;
    const int wm   = wid >> 1;
    const int wn   = wid & 1;
    const int g    = lane >> 2;
    const int tg   = lane & 3;
    const int bm   = blockIdx.x * 128;

    float acc[2][8][4];
#pragma unroll
    for (int mi = 0; mi < 2; mi++)
#pragma unroll
        for (int ni = 0; ni < 8; ni++)
#pragma unroll
            for (int e = 0; e < 4; e++) acc[mi][ni][e] = 0.f;

    for (int k0 = 0; k0 < K; k0 += 32) {
#pragma unroll
        for (int i = 0; i < 4; i++) {
            const int f = tid + i * 256;
            const int row = f >> 3, c4 = (f & 7) * 4;
            const float4 va = *(const float4*)&A[(size_t)(bm + row) * K + k0 + c4];
            As[row][c4 + 0] = tf32_of(va.x); As[row][c4 + 1] = tf32_of(va.y);
            As[row][c4 + 2] = tf32_of(va.z); As[row][c4 + 3] = tf32_of(va.w);
            const float4 vb = *(const float4*)&B[(size_t)row * K + k0 + c4];
            Bs[row][c4 + 0] = tf32_of(vb.x); Bs[row][c4 + 1] = tf32_of(vb.y);
            Bs[row][c4 + 2] = tf32_of(vb.z); Bs[row][c4 + 3] = tf32_of(vb.w);
        }
        __syncthreads();

#pragma unroll
        for (int ks = 0; ks < 4; ks++) {
            const int kb = ks * 8;
            unsigned a[2][4], bf[8][2];
#pragma unroll
            for (int mi = 0; mi < 2; mi++) {
                const int r0 = wm * 32 + mi * 16 + g;
                a[mi][0] = As[r0][kb + tg];
                a[mi][1] = As[r0 + 8][kb + tg];
                a[mi][2] = As[r0][kb + tg + 4];
                a[mi][3] = As[r0 + 8][kb + tg + 4];
            }
#pragma unroll
            for (int ni = 0; ni < 8; ni++) {
                const int n0 = wn * 64 + ni * 8 + g;
                bf[ni][0] = Bs[n0][kb + tg];
                bf[ni][1] = Bs[n0][kb + tg + 4];
            }
#pragma unroll
            for (int mi = 0; mi < 2; mi++)
#pragma unroll
                for (int ni = 0; ni < 8; ni++)
                    mma_tf32(acc[mi][ni], a[mi], bf[ni]);
        }
        __syncthreads();
    }

    float v0s[2][8][2], v1s[2][8][2];
    float sum[2][2], sq[2][2];
#pragma unroll
    for (int mi = 0; mi < 2; mi++) {
        sum[mi][0] = sum[mi][1] = 0.f;
        sq[mi][0]  = sq[mi][1]  = 0.f;
        const int r0 = bm + wm * 32 + mi * 16 + g;
#pragma unroll
        for (int ni = 0; ni < 8; ni++) {
            const int c0 = wn * 64 + ni * 8 + tg * 2;
            const float b0 = bias[c0], b1 = bias[c0 + 1];
            const float2 ra = *(const float2*)&R[(size_t)r0 * CCH + c0];
            const float2 rb = *(const float2*)&R[(size_t)(r0 + 8) * CCH + c0];
            const float x0 = acc[mi][ni][0] + b0 + ra.x;
            const float x1 = acc[mi][ni][1] + b1 + ra.y;
            const float x2 = acc[mi][ni][2] + b0 + rb.x;
            const float x3 = acc[mi][ni][3] + b1 + rb.y;
            v0s[mi][ni][0] = x0; v0s[mi][ni][1] = x1;
            v1s[mi][ni][0] = x2; v1s[mi][ni][1] = x3;
            sum[mi][0] += x0 + x1;         sq[mi][0] += x0*x0 + x1*x1;
            sum[mi][1] += x2 + x3;         sq[mi][1] += x2*x2 + x3*x3;
        }
#pragma unroll
        for (int off = 1; off < 4; off <<= 1) {
            sum[mi][0] += __shfl_xor_sync(0xffffffffu, sum[mi][0], off);
            sq[mi][0]  += __shfl_xor_sync(0xffffffffu, sq[mi][0],  off);
            sum[mi][1] += __shfl_xor_sync(0xffffffffu, sum[mi][1], off);
            sq[mi][1]  += __shfl_xor_sync(0xffffffffu, sq[mi][1],  off);
        }
    }
    if (tg == 0) {
#pragma unroll
        for (int mi = 0; mi < 2; mi++) {
            const int rl = wm * 32 + mi * 16 + g;
            part[wn][rl]     = make_float2(sum[mi][0], sq[mi][0]);
            part[wn][rl + 8] = make_float2(sum[mi][1], sq[mi][1]);
        }
    }
    __syncthreads();

#pragma unroll
    for (int mi = 0; mi < 2; mi++) {
        const int rl = wm * 32 + mi * 16 + g;
#pragma unroll
        for (int half = 0; half < 2; half++) {
            const float2 p0 = part[0][rl + half * 8];
            const float2 p1 = part[1][rl + half * 8];
            const float mu  = (p0.x + p1.x) * (1.f / 128.f);
            const float var = (p0.y + p1.y) * (1.f / 128.f) - mu * mu;
            const float inv = rsqrtf(var + 1e-5f);
            const int row = bm + wm * 32 + mi * 16 + half * 8 + g;
#pragma unroll
            for (int ni = 0; ni < 8; ni++) {
                const int c0 = wn * 64 + ni * 8 + tg * 2;
                const float gv0 = gam[c0], gv1 = gam[c0 + 1];
                const float bv0 = bet[c0], bv1 = bet[c0 + 1];
                const float x0 = (half == 0) ? v0s[mi][ni][0] : v1s[mi][ni][0];
                const float x1 = (half == 0) ? v0s[mi][ni][1] : v1s[mi][ni][1];
                float2 o;
                o.x = (x0 - mu) * inv * gv0 + bv0;
                o.y = (x1 - mu) * inv * gv1 + bv1;
                *(float2*)&out[(size_t)row * CCH + c0] = o;
            }
        }
    }
}

// ---------------------------------------------------------------------------
// 7) tensor-core flash attention. grid (NHEAD, BATCH, 2), 256 threads.
// ---------------------------------------------------------------------------
__global__ __launch_bounds__(256) void attn_kernel()
{
    __shared__ unsigned sK[256][18];
    __shared__ unsigned sV[256][24];

    const int h = blockIdx.x, b = blockIdx.y, qh = blockIdx.z;
    const int tid  = threadIdx.x;
    const int lane = tid & 31;
    const int w    = tid >> 5;
    const int g    = lane >> 2;
    const int tg   = lane & 3;
    const float* qkv = g_qkv + (size_t)b * KTOK * 384;
    const int qbase = qh * 384 + w * 48;

    unsigned qa[3][8];
#pragma unroll
    for (int qt = 0; qt < 3; qt++) {
        const int row = qbase + qt * 16 + g;
        const float* q0 = qkv + (size_t)row * 384 + h * 16;
        const float* q8 = q0 + 8 * 384;
        qa[qt][0] = tf32_of(q0[tg]      * 0.25f);
        qa[qt][1] = tf32_of(q8[tg]      * 0.25f);
        qa[qt][2] = tf32_of(q0[tg + 4]  * 0.25f);
        qa[qt][3] = tf32_of(q8[tg + 4]  * 0.25f);
        qa[qt][4] = tf32_of(q0[tg + 8]  * 0.25f);
        qa[qt][5] = tf32_of(q8[tg + 8]  * 0.25f);
        qa[qt][6] = tf32_of(q0[tg + 12] * 0.25f);
        qa[qt][7] = tf32_of(q8[tg + 12] * 0.25f);
    }

    float m[3][2], l[3][2], o[3][2][4];
#pragma unroll
    for (int qt = 0; qt < 3; qt++) {
        m[qt][0] = m[qt][1] = -1e30f;
        l[qt][0] = l[qt][1] = 0.f;
#pragma unroll
        for (int n = 0; n < 2; n++)
#pragma unroll
            for (int e = 0; e < 4; e++) o[qt][n][e] = 0.f;
    }

    const int src0 = (lane & 28) | (tg >> 1);
    const int src2 = src0 + 2;

    for (int ch = 0; ch < 3; ch++) {
        __syncthreads();
        for (int e = tid; e < 256 * 16; e += 256) {
            const int j = e >> 4, d = e & 15;
            const size_t base = (size_t)(ch * 256 + j) * 384 + h * 16 + d;
            sK[j][d] = tf32_of(qkv[base + 128]);
            sV[j][d] = tf32_of(qkv[base + 256]);
        }
        __syncthreads();

        for (int sub = 0; sub < 8; sub++) {
            unsigned kb[4][2][2];
#pragma unroll
            for (int t = 0; t < 4; t++) {
                const int key = sub * 32 + t * 8 + g;
                kb[t][0][0] = sK[key][tg];
                kb[t][0][1] = sK[key][tg + 4];
                kb[t][1][0] = sK[key][tg + 8];
                kb[t][1][1] = sK[key][tg + 12];
            }
#pragma unroll
            for (int qt = 0; qt < 3; qt++) {
                float s[4][4];
#pragma unroll
                for (int t = 0; t < 4; t++) {
                    s[t][0] = s[t][1] = s[t][2] = s[t][3] = 0.f;
                    mma_tf32(s[t], qa[qt],     kb[t][0]);
                    mma_tf32(s[t], qa[qt] + 4, kb[t][1]);
                }
                float mx0 = s[0][0], mx1 = s[0][2];
#pragma unroll
                for (int t = 0; t < 4; t++) {
                    mx0 = fmaxf(mx0, fmaxf(s[t][0], s[t][1]));
                    mx1 = fmaxf(mx1, fmaxf(s[t][2], s[t][3]));
                }
                mx0 = fmaxf(mx0, __shfl_xor_sync(0xffffffffu, mx0, 1));
                mx0 = fmaxf(mx0, __shfl_xor_sync(0xffffffffu, mx0, 2));
                mx1 = fmaxf(mx1, __shfl_xor_sync(0xffffffffu, mx1, 1));
                mx1 = fmaxf(mx1, __shfl_xor_sync(0xffffffffu, mx1, 2));
                const float nm0 = fmaxf(m[qt][0], mx0);
                const float nm1 = fmaxf(m[qt][1], mx1);
                const float f0 = __expf(m[qt][0] - nm0);
                const float f1 = __expf(m[qt][1] - nm1);
                m[qt][0] = nm0; m[qt][1] = nm1;
                float s0 = 0.f, s1 = 0.f;
#pragma unroll
                for (int t = 0; t < 4; t++) {
                    s[t][0] = tf32f(__expf(s[t][0] - nm0));
                    s[t][1] = tf32f(__expf(s[t][1] - nm0));
                    s[t][2] = tf32f(__expf(s[t][2] - nm1));
                    s[t][3] = tf32f(__expf(s[t][3] - nm1));
                    s0 += s[t][0] + s[t][1];
                    s1 += s[t][2] + s[t][3];
                }
                l[qt][0] = l[qt][0] * f0 + s0;
                l[qt][1] = l[qt][1] * f1 + s1;
#pragma unroll
                for (int n = 0; n < 2; n++) {
                    o[qt][n][0] *= f0; o[qt][n][1] *= f0;
                    o[qt][n][2] *= f1; o[qt][n][3] *= f1;
                }
#pragma unroll
                for (int t = 0; t < 4; t++) {
                    unsigned a[4];
                    {
                        const float t00 = __shfl_sync(0xffffffffu, s[t][0], src0);
                        const float t01 = __shfl_sync(0xffffffffu, s[t][1], src0);
                        const float t10 = __shfl_sync(0xffffffffu, s[t][2], src0);
                        const float t11 = __shfl_sync(0xffffffffu, s[t][3], src0);
                        a[0] = __float_as_uint((tg & 1) ? t01 : t00);
                        a[1] = __float_as_uint((tg & 1) ? t11 : t10);
                        const float u00 = __shfl_sync(0xffffffffu, s[t][0], src2);
                        const float u01 = __shfl_sync(0xffffffffu, s[t][1], src2);
                        const float u10 = __shfl_sync(0xffffffffu, s[t][2], src2);
                        const float u11 = __shfl_sync(0xffffffffu, s[t][3], src2);
                        a[2] = __float_as_uint((tg & 1) ? u01 : u00);
                        a[3] = __float_as_uint((tg & 1) ? u11 : u10);
                    }
                    const int key = sub * 32 + t * 8;
                    unsigned vb0[2], vb1[2];
                    vb0[0] = sV[key + tg][g];         vb0[1] = sV[key + tg + 4][g];
                    vb1[0] = sV[key + tg][g + 8];     vb1[1] = sV[key + tg + 4][g + 8];
                    mma_tf32(o[qt][0], a, vb0);
                    mma_tf32(o[qt][1], a, vb1);
                }
            }
        }
    }

#pragma unroll
    for (int qt = 0; qt < 3; qt++) {
        float l0 = l[qt][0], l1 = l[qt][1];
        l0 += __shfl_xor_sync(0xffffffffu, l0, 1);
        l0 += __shfl_xor_sync(0xffffffffu, l0, 2);
        l1 += __shfl_xor_sync(0xffffffffu, l1, 1);
        l1 += __shfl_xor_sync(0xffffffffu, l1, 2);
        const float inv0 = 1.f / l0, inv1 = 1.f / l1;
        const int row = qbase + qt * 16 + g;
        float* out0 = g_attn + ((size_t)b * KTOK + row) * CCH + h * 16 + tg * 2;
        float* out8 = out0 + 8 * CCH;
#pragma unroll
        for (int n = 0; n < 2; n++) {
            *(float2*)(out0 + n * 8) = make_float2(o[qt][n][0] * inv0, o[qt][n][1] * inv0);
            *(float2*)(out8 + n * 8) = make_float2(o[qt][n][2] * inv1, o[qt][n][3] * inv1);
        }
    }
}

// ---------------------------------------------------------------------------
// 9) finalize: out = x*imp everywhere, except selected pixels take t2.
// ---------------------------------------------------------------------------
__global__ void finalize_kernel(const float* __restrict__ x, float* __restrict__ out)
{
    const unsigned i = blockIdx.x * 256u + threadIdx.x;
    const unsigned total = (unsigned)BATCH * CCH * (PIX / 4);
    if (i >= total) return;
    const unsigned base = i * 4u;
    const unsigned p4 = base % PIX;
    const unsigned bc = base / PIX;
    const unsigned b  = bc / CCH;
    const unsigned c  = bc - b * CCH;
    const float4 xv = *(const float4*)(x + base);
    const float* ip = g_imp + (size_t)b * PIX + p4;
    const int4  iv = *(const int4*)(g_inv + (size_t)b * PIX + p4);
    float4 o;
    o.x = (iv.x >= 0) ? g_t2[((size_t)b * KTOK + iv.x) * CCH + c] : xv.x * ip[0];
    o.y = (iv.y >= 0) ? g_t2[((size_t)b * KTOK + iv.y) * CCH + c] : xv.y * ip[1];
    o.z = (iv.z >= 0) ? g_t2[((size_t)b * KTOK + iv.z) * CCH + c] : xv.z * ip[2];
    o.w = (iv.w >= 0) ? g_t2[((size_t)b * KTOK + iv.w) * CCH + c] : xv.w * ip[3];
    *(float4*)(out + base) = o;
}

// ---------------------------------------------------------------------------
// launch (single stream — overlap attempt in R9 regressed: xs saturates DRAM)
// ---------------------------------------------------------------------------
extern "C" void kernel_launch(void* const* d_in, const int* in_sizes, int n_in,
                              void* d_out, int out_size)
{
    const float* x      = (const float*)d_in[0];
    const float* conv_w = (const float*)d_in[1];
    const float* conv_b = (const float*)d_in[2];
    const float* bn_g   = (const float*)d_in[3];
    const float* bn_b   = (const float*)d_in[4];
    const float* bn_m   = (const float*)d_in[5];
    const float* bn_v   = (const float*)d_in[6];
    const float* w_qkv  = (const float*)d_in[7];
    const float* b_qkv  = (const float*)d_in[8];
    const float* w_o    = (const float*)d_in[9];
    const float* b_o    = (const float*)d_in[10];
    const float* ln1_g  = (const float*)d_in[11];
    const float* ln1_b  = (const float*)d_in[12];
    const float* w1     = (const float*)d_in[13];
    const float* b1     = (const float*)d_in[14];
    const float* w2     = (const float*)d_in[15];
    const float* b2     = (const float*)d_in[16];
    const float* ln2_g  = (const float*)d_in[17];
    const float* ln2_b  = (const float*)d_in[18];
    float* out = (float*)d_out;

    float *p_tokens, *p_qkv, *p_attn, *p_t1, *p_h1, *p_t2;
    cudaGetSymbolAddress((void**)&p_tokens, g_tokens);
    cudaGetSymbolAddress((void**)&p_qkv,    g_qkv);
    cudaGetSymbolAddress((void**)&p_attn,   g_attn);
    cudaGetSymbolAddress((void**)&p_t1,     g_t1);
    cudaGetSymbolAddress((void**)&p_h1,     g_h1);
    cudaGetSymbolAddress((void**)&p_t2,     g_t2);

    const int convgemm_smem = (2 * 64 * 33 + 2 * 32 * 132) * (int)sizeof(unsigned);
    cudaFuncSetAttribute(convgemm_kernel, cudaFuncAttributeMaxDynamicSharedMemorySize,
                         convgemm_smem);
    cudaFuncSetAttribute(topk_kernel, cudaFuncAttributeMaxDynamicSharedMemorySize,
                         PIX * (int)sizeof(unsigned));

    // conv (+ transposed x copy) -> importance -> top-K (+inverse) -> tokens
    freq_kernel<<<1, 64>>>();
    convgemm_kernel<<<dim3(NPT, BATCH), 256, convgemm_smem>>>(x, conv_w);
    convadd_kernel<<<(BATCH * PIX + 255) / 256, 256>>>(conv_b, bn_g, bn_b, bn_m, bn_v);
    topk_kernel<<<BATCH, TKT, PIX * sizeof(unsigned)>>>();
    gather_kernel<<<dim3(KTOK / 2, BATCH), 256>>>();

    // transformer encoder layer (tf32 tensor cores, LN fused into GEMMs)
    gemm_tf32<false><<<dim3(384 / 64, NTOK / 128), 256>>>(p_tokens, w_qkv, b_qkv, p_qkv, NTOK, 384, 128);
    attn_kernel<<<dim3(NHEAD, BATCH, 2), 256>>>();
    gemm_ln<<<NTOK / 128, 256>>>(p_attn, w_o, b_o, p_tokens, ln1_g, ln1_b, p_t1, 128);
    gemm_tf32<true ><<<dim3(256 / 64, NTOK / 128), 256>>>(p_t1, w1, b1, p_h1, NTOK, 256, 128);
    gemm_ln<<<NTOK / 128, 256>>>(p_h1, w2, b2, p_t1, ln2_g, ln2_b, p_t2, 256);

    // assemble output in one pass
    finalize_kernel<<<(BATCH * CCH * (PIX / 4) + 255) / 256, 256>>>(x, out);
}

// round 11
// speedup vs baseline: 1.0744x; 1.0497x over previous
#include <cuda_runtime.h>
#include <cuda_bf16.h>
#include <math.h>

// ---------------------------------------------------------------------------
// Problem constants
// ---------------------------------------------------------------------------
#define BATCH 32
#define CCH   128           // channels / d_model
#define HH    110           // spatial
#define PIX   (HH*HH)       // 12100
#define KTOK  768
#define NHEAD 8
#define HD    16
#define NTOK  (BATCH*KTOK)  // 24576
#define YSTR  112           // padded row stride for y maps
#define CNT   128           // conv GEMM pixel tile
#define NPT   ((PIX + CNT - 1) / CNT)   // 95

typedef unsigned long long u64;

// ---------------------------------------------------------------------------
// helpers
// ---------------------------------------------------------------------------
__device__ __forceinline__ unsigned tf32_of(float x) {
    unsigned r; asm("cvt.rna.tf32.f32 %0, %1;" : "=r"(r) : "f"(x)); return r;
}
__device__ __forceinline__ float tf32f(float x) {
    return __uint_as_float(tf32_of(x));
}
__device__ __forceinline__ void split_tf32(float v, unsigned &hi, unsigned &lo) {
    hi = tf32_of(v);
    lo = tf32_of(v - __uint_as_float(hi));
}
__device__ __forceinline__ void mma_tf32(float* c, const unsigned* a, const unsigned* b) {
    asm("mma.sync.aligned.m16n8k8.row.col.f32.tf32.tf32.f32 "
        "{%0,%1,%2,%3},{%4,%5,%6,%7},{%8,%9},{%0,%1,%2,%3};"
        : "+f"(c[0]), "+f"(c[1]), "+f"(c[2]), "+f"(c[3])
        : "r"(a[0]), "r"(a[1]), "r"(a[2]), "r"(a[3]), "r"(b[0]), "r"(b[1]));
}

// ---------------------------------------------------------------------------
// Scratch (static device globals; no allocation allowed)
// ---------------------------------------------------------------------------
__device__ float g_yt[(size_t)BATCH*49*HH*YSTR];  // per-tap channel-reduced maps
__device__ float g_imp[BATCH*PIX];                // importance map
__device__ int   g_idx[BATCH*KTOK];               // selected pixel indices
__device__ int   g_inv[BATCH*PIX];                // pixel -> token slot (or -1)
__device__ float g_freq[64];                      // positional-encoding freqs
__device__ float g_tokens[NTOK*CCH];
__device__ float g_qkv[NTOK*3*CCH];
__device__ float g_attn[NTOK*CCH];
__device__ float g_t1[NTOK*CCH];
__device__ float g_h1[NTOK*2*CCH];
__device__ float g_t2[NTOK*CCH];

// ---------------------------------------------------------------------------
// 1a) conv as GEMM (3xTF32, fp32-accurate): Y[t][p] = sum_c W[t][c] X[c][p].
//     K-sliced A splits: 49.5 KB smem -> ~4 blocks/SM (32 warps) to hide
//     the scalar-LDS + mma dependency chains. A re-split per chunk is cheap
//     (w is 25 KB, L2-resident).
// ---------------------------------------------------------------------------
__global__ __launch_bounds__(256) void convgemm_kernel(
    const float* __restrict__ x, const float* __restrict__ w)
{
    extern __shared__ unsigned csm[];
    unsigned (*Ah)[33]  = (unsigned(*)[33])csm;                 // 64 x 33
    unsigned (*Al)[33]  = Ah + 64;
    unsigned (*Bh)[132] = (unsigned(*)[132])(csm + 2 * 64 * 33);// 32 x 132
    unsigned (*Bl)[132] = Bh + 32;

    const int pt = blockIdx.x, b = blockIdx.y;
    const int p0 = pt * CNT;
    const int tid = threadIdx.x, lane = tid & 31, wid = tid >> 5;
    const int wm = wid >> 2, wn = wid & 3;
    const int g = lane >> 2, tg = lane & 3;

    float acc[2][4][4];
#pragma unroll
    for (int mi = 0; mi < 2; mi++)
#pragma unroll
        for (int ni = 0; ni < 4; ni++)
#pragma unroll
            for (int e = 0; e < 4; e++) acc[mi][ni][e] = 0.f;

    for (int k0 = 0; k0 < 128; k0 += 32) {
        __syncthreads();
        // A slice: Ah/Al[t][ck] = split(w[(k0+ck)*49 + t]), rows 49..63 zero
        for (int e = tid; e < 64 * 32; e += 256) {
            const int t = e & 63, ck = e >> 6;
            const float v = (t < 49) ? w[(k0 + ck) * 49 + t] : 0.f;
            split_tf32(v, Ah[t][ck], Al[t][ck]);
        }
        // B slice
        for (int e = tid; e < 32 * 128; e += 256) {
            const int c = e >> 7, p = e & 127;
            const int gp = p0 + p;
            const float v = (gp < PIX) ? x[((size_t)b * CCH + k0 + c) * PIX + gp] : 0.f;
            split_tf32(v, Bh[c][p], Bl[c][p]);
        }
        __syncthreads();
#pragma unroll
        for (int ks = 0; ks < 4; ks++) {
            const int kb = ks * 8 + tg;
            unsigned ah[2][4], al[2][4];
#pragma unroll
            for (int mi = 0; mi < 2; mi++) {
                const int rr = wm * 32 + mi * 16 + g;
                ah[mi][0] = Ah[rr][kb];       al[mi][0] = Al[rr][kb];
                ah[mi][1] = Ah[rr + 8][kb];   al[mi][1] = Al[rr + 8][kb];
                ah[mi][2] = Ah[rr][kb + 4];   al[mi][2] = Al[rr][kb + 4];
                ah[mi][3] = Ah[rr + 8][kb+4]; al[mi][3] = Al[rr + 8][kb+4];
            }
#pragma unroll
            for (int ni = 0; ni < 4; ni++) {
                const int n0 = wn * 32 + ni * 8 + g;
                unsigned bh[2], bl[2];
                bh[0] = Bh[kb][n0];     bl[0] = Bl[kb][n0];
                bh[1] = Bh[kb + 4][n0]; bl[1] = Bl[kb + 4][n0];
#pragma unroll
                for (int mi = 0; mi < 2; mi++) {
                    mma_tf32(acc[mi][ni], ah[mi], bh);   // hi*hi
                    mma_tf32(acc[mi][ni], al[mi], bh);   // lo*hi
                    mma_tf32(acc[mi][ni], ah[mi], bl);   // hi*lo
                }
            }
        }
    }

#pragma unroll
    for (int mi = 0; mi < 2; mi++) {
        const int t = wm * 32 + mi * 16 + g;
#pragma unroll
        for (int ni = 0; ni < 4; ni++) {
            const int pcol = p0 + wn * 32 + ni * 8 + tg * 2;
            if (pcol < PIX) {
                const int r0r = pcol / HH, c0r = pcol - r0r * HH;
                const bool ok1 = (pcol + 1 < PIX);
                const int r1r = (pcol + 1) / HH, c1r = (pcol + 1) - r1r * HH;
                if (t < 49) {
                    float* yb = g_yt + ((size_t)b * 49 + t) * HH * YSTR;
                    yb[r0r * YSTR + c0r] = acc[mi][ni][0];
                    if (ok1) yb[r1r * YSTR + c1r] = acc[mi][ni][1];
                }
                if (t + 8 < 49) {
                    float* yb = g_yt + ((size_t)b * 49 + t + 8) * HH * YSTR;
                    yb[r0r * YSTR + c0r] = acc[mi][ni][2];
                    if (ok1) yb[r1r * YSTR + c1r] = acc[mi][ni][3];
                }
            }
        }
    }
}

// ---------------------------------------------------------------------------
// 1b) shift-add over 49 taps + BN + GELU + sigmoid, one thread per pixel.
// ---------------------------------------------------------------------------
__global__ void convadd_kernel(
    const float* __restrict__ cb, const float* __restrict__ bg,
    const float* __restrict__ bb, const float* __restrict__ bm,
    const float* __restrict__ bv)
{
    const int idx = blockIdx.x * 256 + threadIdx.x;
    if (idx >= BATCH * PIX) return;
    const int b = idx / PIX, p = idx - b * PIX;
    const int r = p / HH, c = p - r * HH;
    const float* yb = g_yt + (size_t)b * 49 * HH * YSTR;

    float a = 0.f;
#pragma unroll
    for (int u = 0; u < 7; u++) {
        const int sr = r + 5 * (u - 3);
        if (sr < 0 || sr >= HH) continue;
#pragma unroll
        for (int v = 0; v < 7; v++) {
            const int sc = c + 5 * (v - 3);
            if (sc >= 0 && sc < HH)
                a += yb[((u * 7 + v) * HH + sr) * YSTR + sc];
        }
    }

    const float scale = bg[0] * rsqrtf(bv[0] + 1e-5f);
    float y = a + cb[0];
    y = (y - bm[0]) * scale + bb[0];
    const float gl = 0.5f * y * (1.f + erff(y * 0.70710678118654752f));
    g_imp[idx] = 1.f / (1.f + expf(-gl));
}

// ---------------------------------------------------------------------------
// 3) top-K per batch: radix-256 threshold + ballot compaction. Fills g_inv.
// ---------------------------------------------------------------------------
#define NCHK ((PIX + 255) / 256)   // 48
#define TKT  1024

__global__ __launch_bounds__(TKT) void topk_kernel()
{
    extern __shared__ unsigned sbits[];     // [PIX]
    __shared__ int hist[256];
    __shared__ int cgt[NCHK], ceq[NCHK];
    __shared__ unsigned sh_prefix;
    __shared__ int sh_above;

    const int b    = blockIdx.x;
    const int tid  = threadIdx.x;
    const int lane = tid & 31;
    const int wrp  = tid >> 5;              // 0..31
    const float* v = g_imp + b * PIX;

    for (int i = tid; i < PIX; i += TKT) {
        sbits[i] = __float_as_uint(v[i]);
        g_inv[b * PIX + i] = -1;
    }
    __syncthreads();

    unsigned prefix = 0;
    int kneed = KTOK;

#pragma unroll
    for (int shift = 24; shift >= 0; shift -= 8) {
        if (tid < 256) hist[tid] = 0;
        __syncthreads();
        const unsigned pm = (shift == 24) ? 0u : (0xFFFFFFFFu << (shift + 8));
        for (int i = tid; i < PIX; i += TKT) {
            const unsigned bits = sbits[i];
            if ((bits & pm) == prefix)
                atomicAdd(&hist[(bits >> shift) & 255], 1);
        }
        __syncthreads();
        for (int off = 1; off < 256; off <<= 1) {
            int val = 0;
            if (tid < 256) val = (tid + off < 256) ? hist[tid + off] : 0;
            __syncthreads();
            if (tid < 256) hist[tid] += val;
            __syncthreads();
        }
        if (tid < 256) {
            const int here  = hist[tid];
            const int above = (tid == 255) ? 0 : hist[tid + 1];
            if (here >= kneed && above < kneed) {
                sh_prefix = prefix | ((unsigned)tid << shift);
                sh_above  = above;
            }
        }
        __syncthreads();
        prefix = sh_prefix;
        kneed -= sh_above;
        __syncthreads();
    }

    const unsigned T = prefix;
    const int tn = kneed;                    // ties to take (lowest index first)

    for (int c = wrp; c < NCHK; c += 32) {
        int gt = 0, eq = 0;
#pragma unroll
        for (int g = 0; g < 8; g++) {
            const int i = c * 256 + g * 32 + lane;
            const unsigned bits = (i < PIX) ? sbits[i] : 0u;
            const unsigned bg = __ballot_sync(0xffffffffu, bits > T);
            const unsigned be = __ballot_sync(0xffffffffu, bits == T && i < PIX);
            gt += __popc(bg); eq += __popc(be);
        }
        if (lane == 0) { cgt[c] = gt; ceq[c] = eq; }
    }
    __syncthreads();
    if (tid == 0) {
        int sg = 0, se = 0;
        for (int c = 0; c < NCHK; c++) {
            const int tg2 = cgt[c], te = ceq[c];
            cgt[c] = sg; ceq[c] = se;
            sg += tg2; se += te;
        }
    }
    __syncthreads();

    const unsigned lmask = (1u << lane) - 1u;
    for (int c = wrp; c < NCHK; c += 32) {
        int gt_run = cgt[c], eq_run = ceq[c];
#pragma unroll
        for (int g = 0; g < 8; g++) {
            const int i = c * 256 + g * 32 + lane;
            const unsigned bits = (i < PIX) ? sbits[i] : 0u;
            const bool isgt = bits > T;
            const bool iseq = (bits == T) && (i < PIX);
            const unsigned bg = __ballot_sync(0xffffffffu, isgt);
            const unsigned be = __ballot_sync(0xffffffffu, iseq);
            const int gt_before = gt_run + __popc(bg & lmask);
            const int eq_before = eq_run + __popc(be & lmask);
            int slot = -1;
            if (isgt)                         slot = gt_before + min(eq_before, tn);
            else if (iseq && eq_before < tn)  slot = gt_before + eq_before;
            if (slot >= 0) {
                g_idx[b * KTOK + slot] = i;
                g_inv[b * PIX + i] = slot;
            }
            gt_run += __popc(bg);
            eq_run += __popc(be);
        }
    }
}

// ---------------------------------------------------------------------------
// 4) positional-encoding frequency table
// ---------------------------------------------------------------------------
__global__ void freq_kernel()
{
    const int i = threadIdx.x;           // 64
    const float cst = (float)(-(log(10000.0) / 128.0));
    const float a = (float)(2 * i) * cst;
    g_freq[i] = (float)exp((double)a);
}

// ---------------------------------------------------------------------------
// 5) gather tokens: tokens[b,k,c] = x[b,c,p]*imp[b,p] + PE[p,c]
// ---------------------------------------------------------------------------
__global__ void gather_kernel(const float* __restrict__ x)
{
    const int b = blockIdx.y, k = blockIdx.x, c = threadIdx.x;
    const int p = g_idx[b * KTOK + k];
    const float val = x[((size_t)b * CCH + c) * PIX + p] * g_imp[b * PIX + p];
    const float arg = (float)p * g_freq[c >> 1];
    const float pe  = (c & 1) ? cosf(arg) : sinf(arg);
    g_tokens[((size_t)b * KTOK + k) * CCH + c] = val + pe;
}

// ---------------------------------------------------------------------------
// 6) tf32 tensor-core GEMM: C[m,n] = act( sum_k A[m,k]*B[n,k] + bias[n] )
// ---------------------------------------------------------------------------
template <bool RELU>
__global__ __launch_bounds__(256) void gemm_tf32(
    const float* __restrict__ A, const float* __restrict__ B,
    const float* __restrict__ bias, float* __restrict__ C,
    int M, int N, int K)
{
    __shared__ unsigned As[128][33];
    __shared__ unsigned Bs[64][33];

    const int tid  = threadIdx.x;
    const int lane = tid & 31;
    const int wid  = tid >> 5;
    const int wm   = wid >> 1;
    const int wn   = wid & 1;
    const int g    = lane >> 2;
    const int tg   = lane & 3;
    const int bm   = blockIdx.y * 128, bn = blockIdx.x * 64;

    float acc[2][4][4];
#pragma unroll
    for (int mi = 0; mi < 2; mi++)
#pragma unroll
        for (int ni = 0; ni < 4; ni++)
#pragma unroll
            for (int e = 0; e < 4; e++) acc[mi][ni][e] = 0.f;

    for (int k0 = 0; k0 < K; k0 += 32) {
#pragma unroll
        for (int i = 0; i < 4; i++) {
            const int f = tid + i * 256;
            const int row = f >> 3, c4 = (f & 7) * 4;
            const float4 v = *(const float4*)&A[(size_t)(bm + row) * K + k0 + c4];
            As[row][c4 + 0] = tf32_of(v.x); As[row][c4 + 1] = tf32_of(v.y);
            As[row][c4 + 2] = tf32_of(v.z); As[row][c4 + 3] = tf32_of(v.w);
        }
#pragma unroll
        for (int i = 0; i < 2; i++) {
            const int f = tid + i * 256;
            const int row = f >> 3, c4 = (f & 7) * 4;
            const float4 v = *(const float4*)&B[(size_t)(bn + row) * K + k0 + c4];
            Bs[row][c4 + 0] = tf32_of(v.x); Bs[row][c4 + 1] = tf32_of(v.y);
            Bs[row][c4 + 2] = tf32_of(v.z); Bs[row][c4 + 3] = tf32_of(v.w);
        }
        __syncthreads();

#pragma unroll
        for (int ks = 0; ks < 4; ks++) {
            const int kb = ks * 8;
            unsigned a[2][4], bf[4][2];
#pragma unroll
            for (int mi = 0; mi < 2; mi++) {
                const int r0 = wm * 32 + mi * 16 + g;
                a[mi][0] = As[r0][kb + tg];
                a[mi][1] = As[r0 + 8][kb + tg];
                a[mi][2] = As[r0][kb + tg + 4];
                a[mi][3] = As[r0 + 8][kb + tg + 4];
            }
#pragma unroll
            for (int ni = 0; ni < 4; ni++) {
                const int n0 = wn * 32 + ni * 8 + g;
                bf[ni][0] = Bs[n0][kb + tg];
                bf[ni][1] = Bs[n0][kb + tg + 4];
            }
#pragma unroll
            for (int mi = 0; mi < 2; mi++)
#pragma unroll
                for (int ni = 0; ni < 4; ni++)
                    mma_tf32(acc[mi][ni], a[mi], bf[ni]);
        }
        __syncthreads();
    }

#pragma unroll
    for (int mi = 0; mi < 2; mi++) {
        const int r0 = bm + wm * 32 + mi * 16 + g;
#pragma unroll
        for (int ni = 0; ni < 4; ni++) {
            const int c0 = bn + wn * 32 + ni * 8 + tg * 2;
            const float b0 = bias[c0], b1 = bias[c0 + 1];
            float2 v0 = { acc[mi][ni][0] + b0, acc[mi][ni][1] + b1 };
            float2 v1 = { acc[mi][ni][2] + b0, acc[mi][ni][3] + b1 };
            if (RELU) {
                v0.x = fmaxf(v0.x, 0.f); v0.y = fmaxf(v0.y, 0.f);
                v1.x = fmaxf(v1.x, 0.f); v1.y = fmaxf(v1.y, 0.f);
            }
            *(float2*)&C[(size_t)r0 * N + c0]       = v0;
            *(float2*)&C[(size_t)(r0 + 8) * N + c0] = v1;
        }
    }
}

// ---------------------------------------------------------------------------
// 6b) fused GEMM + bias + residual + LayerNorm. BN = 128 = full d_model.
// ---------------------------------------------------------------------------
__global__ __launch_bounds__(256) void gemm_ln(
    const float* __restrict__ A, const float* __restrict__ B,
    const float* __restrict__ bias, const float* __restrict__ R,
    const float* __restrict__ gam, const float* __restrict__ bet,
    float* __restrict__ out, int K)
{
    __shared__ unsigned As[128][33];
    __shared__ unsigned Bs[128][33];
    __shared__ float2 part[2][128];

    const int tid  = threadIdx.x;
    const int lane = tid & 31;
    const int wid  = tid >> 5;
    const int wm   = wid >> 1;
    const int wn   = wid & 1;
    const int g    = lane >> 2;
    const int tg   = lane & 3;
    const int bm   = blockIdx.x * 128;

    float acc[2][8][4];
#pragma unroll
    for (int mi = 0; mi < 2; mi++)
#pragma unroll
        for (int ni = 0; ni < 8; ni++)
#pragma unroll
            for (int e = 0; e < 4; e++) acc[mi][ni][e] = 0.f;

    for (int k0 = 0; k0 < K; k0 += 32) {
#pragma unroll
        for (int i = 0; i < 4; i++) {
            const int f = tid + i * 256;
            const int row = f >> 3, c4 = (f & 7) * 4;
            const float4 va = *(const float4*)&A[(size_t)(bm + row) * K + k0 + c4];
            As[row][c4 + 0] = tf32_of(va.x); As[row][c4 + 1] = tf32_of(va.y);
            As[row][c4 + 2] = tf32_of(va.z); As[row][c4 + 3] = tf32_of(va.w);
            const float4 vb = *(const float4*)&B[(size_t)row * K + k0 + c4];
            Bs[row][c4 + 0] = tf32_of(vb.x); Bs[row][c4 + 1] = tf32_of(vb.y);
            Bs[row][c4 + 2] = tf32_of(vb.z); Bs[row][c4 + 3] = tf32_of(vb.w);
        }
        __syncthreads();

#pragma unroll
        for (int ks = 0; ks < 4; ks++) {
            const int kb = ks * 8;
            unsigned a[2][4], bf[8][2];
#pragma unroll
            for (int mi = 0; mi < 2; mi++) {
                const int r0 = wm * 32 + mi * 16 + g;
                a[mi][0] = As[r0][kb + tg];
                a[mi][1] = As[r0 + 8][kb + tg];
                a[mi][2] = As[r0][kb + tg + 4];
                a[mi][3] = As[r0 + 8][kb + tg + 4];
            }
#pragma unroll
            for (int ni = 0; ni < 8; ni++) {
                const int n0 = wn * 64 + ni * 8 + g;
                bf[ni][0] = Bs[n0][kb + tg];
                bf[ni][1] = Bs[n0][kb + tg + 4];
            }
#pragma unroll
            for (int mi = 0; mi < 2; mi++)
#pragma unroll
                for (int ni = 0; ni < 8; ni++)
                    mma_tf32(acc[mi][ni], a[mi], bf[ni]);
        }
        __syncthreads();
    }

    float v0s[2][8][2], v1s[2][8][2];
    float sum[2][2], sq[2][2];
#pragma unroll
    for (int mi = 0; mi < 2; mi++) {
        sum[mi][0] = sum[mi][1] = 0.f;
        sq[mi][0]  = sq[mi][1]  = 0.f;
        const int r0 = bm + wm * 32 + mi * 16 + g;
#pragma unroll
        for (int ni = 0; ni < 8; ni++) {
            const int c0 = wn * 64 + ni * 8 + tg * 2;
            const float b0 = bias[c0], b1 = bias[c0 + 1];
            const float2 ra = *(const float2*)&R[(size_t)r0 * CCH + c0];
            const float2 rb = *(const float2*)&R[(size_t)(r0 + 8) * CCH + c0];
            const float x0 = acc[mi][ni][0] + b0 + ra.x;
            const float x1 = acc[mi][ni][1] + b1 + ra.y;
            const float x2 = acc[mi][ni][2] + b0 + rb.x;
            const float x3 = acc[mi][ni][3] + b1 + rb.y;
            v0s[mi][ni][0] = x0; v0s[mi][ni][1] = x1;
            v1s[mi][ni][0] = x2; v1s[mi][ni][1] = x3;
            sum[mi][0] += x0 + x1;         sq[mi][0] += x0*x0 + x1*x1;
            sum[mi][1] += x2 + x3;         sq[mi][1] += x2*x2 + x3*x3;
        }
#pragma unroll
        for (int off = 1; off < 4; off <<= 1) {
            sum[mi][0] += __shfl_xor_sync(0xffffffffu, sum[mi][0], off);
            sq[mi][0]  += __shfl_xor_sync(0xffffffffu, sq[mi][0],  off);
            sum[mi][1] += __shfl_xor_sync(0xffffffffu, sum[mi][1], off);
            sq[mi][1]  += __shfl_xor_sync(0xffffffffu, sq[mi][1],  off);
        }
    }
    if (tg == 0) {
#pragma unroll
        for (int mi = 0; mi < 2; mi++) {
            const int rl = wm * 32 + mi * 16 + g;
            part[wn][rl]     = make_float2(sum[mi][0], sq[mi][0]);
            part[wn][rl + 8] = make_float2(sum[mi][1], sq[mi][1]);
        }
    }
    __syncthreads();

#pragma unroll
    for (int mi = 0; mi < 2; mi++) {
        const int rl = wm * 32 + mi * 16 + g;
#pragma unroll
        for (int half = 0; half < 2; half++) {
            const float2 p0 = part[0][rl + half * 8];
            const float2 p1 = part[1][rl + half * 8];
            const float mu  = (p0.x + p1.x) * (1.f / 128.f);
            const float var = (p0.y + p1.y) * (1.f / 128.f) - mu * mu;
            const float inv = rsqrtf(var + 1e-5f);
            const int row = bm + wm * 32 + mi * 16 + half * 8 + g;
#pragma unroll
            for (int ni = 0; ni < 8; ni++) {
                const int c0 = wn * 64 + ni * 8 + tg * 2;
                const float gv0 = gam[c0], gv1 = gam[c0 + 1];
                const float bv0 = bet[c0], bv1 = bet[c0 + 1];
                const float x0 = (half == 0) ? v0s[mi][ni][0] : v1s[mi][ni][0];
                const float x1 = (half == 0) ? v0s[mi][ni][1] : v1s[mi][ni][1];
                float2 o;
                o.x = (x0 - mu) * inv * gv0 + bv0;
                o.y = (x1 - mu) * inv * gv1 + bv1;
                *(float2*)&out[(size_t)row * CCH + c0] = o;
            }
        }
    }
}

// ---------------------------------------------------------------------------
// 7) tensor-core flash attention. grid (NHEAD, BATCH, 2), 256 threads.
// ---------------------------------------------------------------------------
__global__ __launch_bounds__(256) void attn_kernel()
{
    __shared__ unsigned sK[256][18];
    __shared__ unsigned sV[256][24];

    const int h = blockIdx.x, b = blockIdx.y, qh = blockIdx.z;
    const int tid  = threadIdx.x;
    const int lane = tid & 31;
    const int w    = tid >> 5;
    const int g    = lane >> 2;
    const int tg   = lane & 3;
    const float* qkv = g_qkv + (size_t)b * KTOK * 384;
    const int qbase = qh * 384 + w * 48;

    unsigned qa[3][8];
#pragma unroll
    for (int qt = 0; qt < 3; qt++) {
        const int row = qbase + qt * 16 + g;
        const float* q0 = qkv + (size_t)row * 384 + h * 16;
        const float* q8 = q0 + 8 * 384;
        qa[qt][0] = tf32_of(q0[tg]      * 0.25f);
        qa[qt][1] = tf32_of(q8[tg]      * 0.25f);
        qa[qt][2] = tf32_of(q0[tg + 4]  * 0.25f);
        qa[qt][3] = tf32_of(q8[tg + 4]  * 0.25f);
        qa[qt][4] = tf32_of(q0[tg + 8]  * 0.25f);
        qa[qt][5] = tf32_of(q8[tg + 8]  * 0.25f);
        qa[qt][6] = tf32_of(q0[tg + 12] * 0.25f);
        qa[qt][7] = tf32_of(q8[tg + 12] * 0.25f);
    }

    float m[3][2], l[3][2], o[3][2][4];
#pragma unroll
    for (int qt = 0; qt < 3; qt++) {
        m[qt][0] = m[qt][1] = -1e30f;
        l[qt][0] = l[qt][1] = 0.f;
#pragma unroll
        for (int n = 0; n < 2; n++)
#pragma unroll
            for (int e = 0; e < 4; e++) o[qt][n][e] = 0.f;
    }

    const int src0 = (lane & 28) | (tg >> 1);
    const int src2 = src0 + 2;

    for (int ch = 0; ch < 3; ch++) {
        __syncthreads();
        for (int e = tid; e < 256 * 16; e += 256) {
            const int j = e >> 4, d = e & 15;
            const size_t base = (size_t)(ch * 256 + j) * 384 + h * 16 + d;
            sK[j][d] = tf32_of(qkv[base + 128]);
            sV[j][d] = tf32_of(qkv[base + 256]);
        }
        __syncthreads();

        for (int sub = 0; sub < 8; sub++) {
            unsigned kb[4][2][2];
#pragma unroll
            for (int t = 0; t < 4; t++) {
                const int key = sub * 32 + t * 8 + g;
                kb[t][0][0] = sK[key][tg];
                kb[t][0][1] = sK[key][tg + 4];
                kb[t][1][0] = sK[key][tg + 8];
                kb[t][1][1] = sK[key][tg + 12];
            }
#pragma unroll
            for (int qt = 0; qt < 3; qt++) {
                float s[4][4];
#pragma unroll
                for (int t = 0; t < 4; t++) {
                    s[t][0] = s[t][1] = s[t][2] = s[t][3] = 0.f;
                    mma_tf32(s[t], qa[qt],     kb[t][0]);
                    mma_tf32(s[t], qa[qt] + 4, kb[t][1]);
                }
                float mx0 = s[0][0], mx1 = s[0][2];
#pragma unroll
                for (int t = 0; t < 4; t++) {
                    mx0 = fmaxf(mx0, fmaxf(s[t][0], s[t][1]));
                    mx1 = fmaxf(mx1, fmaxf(s[t][2], s[t][3]));
                }
                mx0 = fmaxf(mx0, __shfl_xor_sync(0xffffffffu, mx0, 1));
                mx0 = fmaxf(mx0, __shfl_xor_sync(0xffffffffu, mx0, 2));
                mx1 = fmaxf(mx1, __shfl_xor_sync(0xffffffffu, mx1, 1));
                mx1 = fmaxf(mx1, __shfl_xor_sync(0xffffffffu, mx1, 2));
                const float nm0 = fmaxf(m[qt][0], mx0);
                const float nm1 = fmaxf(m[qt][1], mx1);
                const float f0 = __expf(m[qt][0] - nm0);
                const float f1 = __expf(m[qt][1] - nm1);
                m[qt][0] = nm0; m[qt][1] = nm1;
                float s0 = 0.f, s1 = 0.f;
#pragma unroll
                for (int t = 0; t < 4; t++) {
                    s[t][0] = tf32f(__expf(s[t][0] - nm0));
                    s[t][1] = tf32f(__expf(s[t][1] - nm0));
                    s[t][2] = tf32f(__expf(s[t][2] - nm1));
                    s[t][3] = tf32f(__expf(s[t][3] - nm1));
                    s0 += s[t][0] + s[t][1];
                    s1 += s[t][2] + s[t][3];
                }
                l[qt][0] = l[qt][0] * f0 + s0;
                l[qt][1] = l[qt][1] * f1 + s1;
#pragma unroll
                for (int n = 0; n < 2; n++) {
                    o[qt][n][0] *= f0; o[qt][n][1] *= f0;
                    o[qt][n][2] *= f1; o[qt][n][3] *= f1;
                }
#pragma unroll
                for (int t = 0; t < 4; t++) {
                    unsigned a[4];
                    {
                        const float t00 = __shfl_sync(0xffffffffu, s[t][0], src0);
                        const float t01 = __shfl_sync(0xffffffffu, s[t][1], src0);
                        const float t10 = __shfl_sync(0xffffffffu, s[t][2], src0);
                        const float t11 = __shfl_sync(0xffffffffu, s[t][3], src0);
                        a[0] = __float_as_uint((tg & 1) ? t01 : t00);
                        a[1] = __float_as_uint((tg & 1) ? t11 : t10);
                        const float u00 = __shfl_sync(0xffffffffu, s[t][0], src2);
                        const float u01 = __shfl_sync(0xffffffffu, s[t][1], src2);
                        const float u10 = __shfl_sync(0xffffffffu, s[t][2], src2);
                        const float u11 = __shfl_sync(0xffffffffu, s[t][3], src2);
                        a[2] = __float_as_uint((tg & 1) ? u01 : u00);
                        a[3] = __float_as_uint((tg & 1) ? u11 : u10);
                    }
                    const int key = sub * 32 + t * 8;
                    unsigned vb0[2], vb1[2];
                    vb0[0] = sV[key + tg][g];         vb0[1] = sV[key + tg + 4][g];
                    vb1[0] = sV[key + tg][g + 8];     vb1[1] = sV[key + tg + 4][g + 8];
                    mma_tf32(o[qt][0], a, vb0);
                    mma_tf32(o[qt][1], a, vb1);
                }
            }
        }
    }

#pragma unroll
    for (int qt = 0; qt < 3; qt++) {
        float l0 = l[qt][0], l1 = l[qt][1];
        l0 += __shfl_xor_sync(0xffffffffu, l0, 1);
        l0 += __shfl_xor_sync(0xffffffffu, l0, 2);
        l1 += __shfl_xor_sync(0xffffffffu, l1, 1);
        l1 += __shfl_xor_sync(0xffffffffu, l1, 2);
        const float inv0 = 1.f / l0, inv1 = 1.f / l1;
        const int row = qbase + qt * 16 + g;
        float* out0 = g_attn + ((size_t)b * KTOK + row) * CCH + h * 16 + tg * 2;
        float* out8 = out0 + 8 * CCH;
#pragma unroll
        for (int n = 0; n < 2; n++) {
            *(float2*)(out0 + n * 8) = make_float2(o[qt][n][0] * inv0, o[qt][n][1] * inv0);
            *(float2*)(out8 + n * 8) = make_float2(o[qt][n][2] * inv1, o[qt][n][3] * inv1);
        }
    }
}

// ---------------------------------------------------------------------------
// 9) finalize: out = x*imp everywhere, except selected pixels take t2.
// ---------------------------------------------------------------------------
__global__ void finalize_kernel(const float* __restrict__ x, float* __restrict__ out)
{
    const unsigned i = blockIdx.x * 256u + threadIdx.x;
    const unsigned total = (unsigned)BATCH * CCH * (PIX / 4);
    if (i >= total) return;
    const unsigned base = i * 4u;
    const unsigned p4 = base % PIX;
    const unsigned bc = base / PIX;
    const unsigned b  = bc / CCH;
    const unsigned c  = bc - b * CCH;
    const float4 xv = *(const float4*)(x + base);
    const float* ip = g_imp + (size_t)b * PIX + p4;
    const int4  iv = *(const int4*)(g_inv + (size_t)b * PIX + p4);
    float4 o;
    o.x = (iv.x >= 0) ? g_t2[((size_t)b * KTOK + iv.x) * CCH + c] : xv.x * ip[0];
    o.y = (iv.y >= 0) ? g_t2[((size_t)b * KTOK + iv.y) * CCH + c] : xv.y * ip[1];
    o.z = (iv.z >= 0) ? g_t2[((size_t)b * KTOK + iv.z) * CCH + c] : xv.z * ip[2];
    o.w = (iv.w >= 0) ? g_t2[((size_t)b * KTOK + iv.w) * CCH + c] : xv.w * ip[3];
    *(float4*)(out + base) = o;
}

// ---------------------------------------------------------------------------
// launch (single stream; R8 structure + K-sliced convgemm only)
// ---------------------------------------------------------------------------
extern "C" void kernel_launch(void* const* d_in, const int* in_sizes, int n_in,
                              void* d_out, int out_size)
{
    const float* x      = (const float*)d_in[0];
    const float* conv_w = (const float*)d_in[1];
    const float* conv_b = (const float*)d_in[2];
    const float* bn_g   = (const float*)d_in[3];
    const float* bn_b   = (const float*)d_in[4];
    const float* bn_m   = (const float*)d_in[5];
    const float* bn_v   = (const float*)d_in[6];
    const float* w_qkv  = (const float*)d_in[7];
    const float* b_qkv  = (const float*)d_in[8];
    const float* w_o    = (const float*)d_in[9];
    const float* b_o    = (const float*)d_in[10];
    const float* ln1_g  = (const float*)d_in[11];
    const float* ln1_b  = (const float*)d_in[12];
    const float* w1     = (const float*)d_in[13];
    const float* b1     = (const float*)d_in[14];
    const float* w2     = (const float*)d_in[15];
    const float* b2     = (const float*)d_in[16];
    const float* ln2_g  = (const float*)d_in[17];
    const float* ln2_b  = (const float*)d_in[18];
    float* out = (float*)d_out;

    float *p_tokens, *p_qkv, *p_attn, *p_t1, *p_h1, *p_t2;
    cudaGetSymbolAddress((void**)&p_tokens, g_tokens);
    cudaGetSymbolAddress((void**)&p_qkv,    g_qkv);
    cudaGetSymbolAddress((void**)&p_attn,   g_attn);
    cudaGetSymbolAddress((void**)&p_t1,     g_t1);
    cudaGetSymbolAddress((void**)&p_h1,     g_h1);
    cudaGetSymbolAddress((void**)&p_t2,     g_t2);

    const int convgemm_smem = (2 * 64 * 33 + 2 * 32 * 132) * (int)sizeof(unsigned);
    cudaFuncSetAttribute(convgemm_kernel, cudaFuncAttributeMaxDynamicSharedMemorySize,
                         convgemm_smem);
    cudaFuncSetAttribute(topk_kernel, cudaFuncAttributeMaxDynamicSharedMemorySize,
                         PIX * (int)sizeof(unsigned));

    // conv -> importance -> top-K (+inverse map) -> tokens
    freq_kernel<<<1, 64>>>();
    convgemm_kernel<<<dim3(NPT, BATCH), 256, convgemm_smem>>>(x, conv_w);
    convadd_kernel<<<(BATCH * PIX + 255) / 256, 256>>>(conv_b, bn_g, bn_b, bn_m, bn_v);
    topk_kernel<<<BATCH, TKT, PIX * sizeof(unsigned)>>>();
    gather_kernel<<<dim3(KTOK, BATCH), CCH>>>(x);

    // transformer encoder layer (tf32 tensor cores, LN fused into GEMMs)
    gemm_tf32<false><<<dim3(384 / 64, NTOK / 128), 256>>>(p_tokens, w_qkv, b_qkv, p_qkv, NTOK, 384, 128);
    attn_kernel<<<dim3(NHEAD, BATCH, 2), 256>>>();
    gemm_ln<<<NTOK / 128, 256>>>(p_attn, w_o, b_o, p_tokens, ln1_g, ln1_b, p_t1, 128);
    gemm_tf32<true ><<<dim3(256 / 64, NTOK / 128), 256>>>(p_t1, w1, b1, p_h1, NTOK, 256, 128);
    gemm_ln<<<NTOK / 128, 256>>>(p_h1, w2, b2, p_t1, ln2_g, ln2_b, p_t2, 256);

    // assemble output in one pass
    finalize_kernel<<<(BATCH * CCH * (PIX / 4) + 255) / 256, 256>>>(x, out);
}

// round 12
// speedup vs baseline: 1.1030x; 1.0265x over previous
#include <cuda_runtime.h>
#include <cuda_bf16.h>
#include <math.h>

// ---------------------------------------------------------------------------
// Problem constants
// ---------------------------------------------------------------------------
#define BATCH 32
#define CCH   128           // channels / d_model
#define HH    110           // spatial
#define PIX   (HH*HH)       // 12100
#define KTOK  768
#define NHEAD 8
#define HD    16
#define NTOK  (BATCH*KTOK)  // 24576
#define YSTR  112           // padded row stride for y maps
#define CNT   128           // conv GEMM pixel tile
#define NPT   ((PIX + CNT - 1) / CNT)   // 95

typedef unsigned long long u64;

// ---------------------------------------------------------------------------
// helpers
// ---------------------------------------------------------------------------
__device__ __forceinline__ unsigned tf32_of(float x) {
    unsigned r; asm("cvt.rna.tf32.f32 %0, %1;" : "=r"(r) : "f"(x)); return r;
}
__device__ __forceinline__ float tf32f(float x) {
    return __uint_as_float(tf32_of(x));
}
__device__ __forceinline__ void split_tf32(float v, unsigned &hi, unsigned &lo) {
    hi = tf32_of(v);
    lo = tf32_of(v - __uint_as_float(hi));
}
__device__ __forceinline__ void mma_tf32(float* c, const unsigned* a, const unsigned* b) {
    asm("mma.sync.aligned.m16n8k8.row.col.f32.tf32.tf32.f32 "
        "{%0,%1,%2,%3},{%4,%5,%6,%7},{%8,%9},{%0,%1,%2,%3};"
        : "+f"(c[0]), "+f"(c[1]), "+f"(c[2]), "+f"(c[3])
        : "r"(a[0]), "r"(a[1]), "r"(a[2]), "r"(a[3]), "r"(b[0]), "r"(b[1]));
}

// ---------------------------------------------------------------------------
// Scratch (static device globals; no allocation allowed)
// ---------------------------------------------------------------------------
__device__ float g_yt[(size_t)BATCH*49*HH*YSTR];  // per-tap channel-reduced maps
__device__ float g_imp[BATCH*PIX];                // importance map
__device__ int   g_idx[BATCH*KTOK];               // selected pixel indices
__device__ int   g_inv[BATCH*PIX];                // pixel -> token slot (or -1)
__device__ float g_freq[64];                      // positional-encoding freqs
__device__ float g_tokens[NTOK*CCH];
__device__ float g_qkv[NTOK*3*CCH];
__device__ float g_attn[NTOK*CCH];
__device__ float g_t1[NTOK*CCH];
__device__ float g_h1[NTOK*2*CCH];
__device__ float g_t2[NTOK*CCH];

// ---------------------------------------------------------------------------
// 1a) conv as GEMM (3xTF32, fp32-accurate), R8 variant (hoisted splits).
// ---------------------------------------------------------------------------
__global__ __launch_bounds__(256) void convgemm_kernel(
    const float* __restrict__ x, const float* __restrict__ w)
{
    extern __shared__ unsigned csm[];
    unsigned (*Ah)[132] = (unsigned(*)[132])csm;            // 64 x 132
    unsigned (*Al)[132] = Ah + 64;
    unsigned (*Bh)[132] = Al + 64;                          // 32 x 132
    unsigned (*Bl)[132] = Bh + 32;

    const int pt = blockIdx.x, b = blockIdx.y;
    const int p0 = pt * CNT;
    const int tid = threadIdx.x, lane = tid & 31, wid = tid >> 5;
    const int wm = wid >> 2, wn = wid & 3;
    const int g = lane >> 2, tg = lane & 3;

    for (int e = tid; e < 64 * 128; e += 256) {
        const int t = e & 63, c = e >> 6;
        const float v = (t < 49) ? w[c * 49 + t] : 0.f;
        split_tf32(v, Ah[t][c], Al[t][c]);
    }

    float acc[2][4][4];
#pragma unroll
    for (int mi = 0; mi < 2; mi++)
#pragma unroll
        for (int ni = 0; ni < 4; ni++)
#pragma unroll
            for (int e = 0; e < 4; e++) acc[mi][ni][e] = 0.f;

    for (int k0 = 0; k0 < 128; k0 += 32) {
        __syncthreads();
        for (int e = tid; e < 32 * 128; e += 256) {
            const int c = e >> 7, p = e & 127;
            const int gp = p0 + p;
            const float v = (gp < PIX) ? x[((size_t)b * CCH + k0 + c) * PIX + gp] : 0.f;
            split_tf32(v, Bh[c][p], Bl[c][p]);
        }
        __syncthreads();
#pragma unroll
        for (int ks = 0; ks < 4; ks++) {
            const int kk = k0 + ks * 8 + tg;
            const int kb = ks * 8 + tg;
            unsigned ah[2][4], al[2][4];
#pragma unroll
            for (int mi = 0; mi < 2; mi++) {
                const int rr = wm * 32 + mi * 16 + g;
                ah[mi][0] = Ah[rr][kk];      al[mi][0] = Al[rr][kk];
                ah[mi][1] = Ah[rr + 8][kk];  al[mi][1] = Al[rr + 8][kk];
                ah[mi][2] = Ah[rr][kk + 4];  al[mi][2] = Al[rr][kk + 4];
                ah[mi][3] = Ah[rr + 8][kk+4];al[mi][3] = Al[rr + 8][kk+4];
            }
#pragma unroll
            for (int ni = 0; ni < 4; ni++) {
                const int n0 = wn * 32 + ni * 8 + g;
                unsigned bh[2], bl[2];
                bh[0] = Bh[kb][n0];     bl[0] = Bl[kb][n0];
                bh[1] = Bh[kb + 4][n0]; bl[1] = Bl[kb + 4][n0];
#pragma unroll
                for (int mi = 0; mi < 2; mi++) {
                    mma_tf32(acc[mi][ni], ah[mi], bh);
                    mma_tf32(acc[mi][ni], al[mi], bh);
                    mma_tf32(acc[mi][ni], ah[mi], bl);
                }
            }
        }
    }

#pragma unroll
    for (int mi = 0; mi < 2; mi++) {
        const int t = wm * 32 + mi * 16 + g;
#pragma unroll
        for (int ni = 0; ni < 4; ni++) {
            const int pcol = p0 + wn * 32 + ni * 8 + tg * 2;
            if (pcol < PIX) {
                const int r0r = pcol / HH, c0r = pcol - r0r * HH;
                const bool ok1 = (pcol + 1 < PIX);
                const int r1r = (pcol + 1) / HH, c1r = (pcol + 1) - r1r * HH;
                if (t < 49) {
                    float* yb = g_yt + ((size_t)b * 49 + t) * HH * YSTR;
                    yb[r0r * YSTR + c0r] = acc[mi][ni][0];
                    if (ok1) yb[r1r * YSTR + c1r] = acc[mi][ni][1];
                }
                if (t + 8 < 49) {
                    float* yb = g_yt + ((size_t)b * 49 + t + 8) * HH * YSTR;
                    yb[r0r * YSTR + c0r] = acc[mi][ni][2];
                    if (ok1) yb[r1r * YSTR + c1r] = acc[mi][ni][3];
                }
            }
        }
    }
}

// ---------------------------------------------------------------------------
// 1b) shift-add over 49 taps + BN + GELU + sigmoid, one thread per pixel.
// ---------------------------------------------------------------------------
__global__ void convadd_kernel(
    const float* __restrict__ cb, const float* __restrict__ bg,
    const float* __restrict__ bb, const float* __restrict__ bm,
    const float* __restrict__ bv)
{
    const int idx = blockIdx.x * 256 + threadIdx.x;
    if (idx >= BATCH * PIX) return;
    const int b = idx / PIX, p = idx - b * PIX;
    const int r = p / HH, c = p - r * HH;
    const float* yb = g_yt + (size_t)b * 49 * HH * YSTR;

    float a = 0.f;
#pragma unroll
    for (int u = 0; u < 7; u++) {
        const int sr = r + 5 * (u - 3);
        if (sr < 0 || sr >= HH) continue;
#pragma unroll
        for (int v = 0; v < 7; v++) {
            const int sc = c + 5 * (v - 3);
            if (sc >= 0 && sc < HH)
                a += yb[((u * 7 + v) * HH + sr) * YSTR + sc];
        }
    }

    const float scale = bg[0] * rsqrtf(bv[0] + 1e-5f);
    float y = a + cb[0];
    y = (y - bm[0]) * scale + bb[0];
    const float gl = 0.5f * y * (1.f + erff(y * 0.70710678118654752f));
    g_imp[idx] = 1.f / (1.f + expf(-gl));
}

// ---------------------------------------------------------------------------
// 3) top-K per batch: radix-256 threshold + ballot compaction. Fills g_inv.
// ---------------------------------------------------------------------------
#define NCHK ((PIX + 255) / 256)   // 48
#define TKT  1024

__global__ __launch_bounds__(TKT) void topk_kernel()
{
    extern __shared__ unsigned sbits[];     // [PIX]
    __shared__ int hist[256];
    __shared__ int cgt[NCHK], ceq[NCHK];
    __shared__ unsigned sh_prefix;
    __shared__ int sh_above;

    const int b    = blockIdx.x;
    const int tid  = threadIdx.x;
    const int lane = tid & 31;
    const int wrp  = tid >> 5;              // 0..31
    const float* v = g_imp + b * PIX;

    for (int i = tid; i < PIX; i += TKT) {
        sbits[i] = __float_as_uint(v[i]);
        g_inv[b * PIX + i] = -1;
    }
    __syncthreads();

    unsigned prefix = 0;
    int kneed = KTOK;

#pragma unroll
    for (int shift = 24; shift >= 0; shift -= 8) {
        if (tid < 256) hist[tid] = 0;
        __syncthreads();
        const unsigned pm = (shift == 24) ? 0u : (0xFFFFFFFFu << (shift + 8));
        for (int i = tid; i < PIX; i += TKT) {
            const unsigned bits = sbits[i];
            if ((bits & pm) == prefix)
                atomicAdd(&hist[(bits >> shift) & 255], 1);
        }
        __syncthreads();
        for (int off = 1; off < 256; off <<= 1) {
            int val = 0;
            if (tid < 256) val = (tid + off < 256) ? hist[tid + off] : 0;
            __syncthreads();
            if (tid < 256) hist[tid] += val;
            __syncthreads();
        }
        if (tid < 256) {
            const int here  = hist[tid];
            const int above = (tid == 255) ? 0 : hist[tid + 1];
            if (here >= kneed && above < kneed) {
                sh_prefix = prefix | ((unsigned)tid << shift);
                sh_above  = above;
            }
        }
        __syncthreads();
        prefix = sh_prefix;
        kneed -= sh_above;
        __syncthreads();
    }

    const unsigned T = prefix;
    const int tn = kneed;                    // ties to take (lowest index first)

    for (int c = wrp; c < NCHK; c += 32) {
        int gt = 0, eq = 0;
#pragma unroll
        for (int g = 0; g < 8; g++) {
            const int i = c * 256 + g * 32 + lane;
            const unsigned bits = (i < PIX) ? sbits[i] : 0u;
            const unsigned bg = __ballot_sync(0xffffffffu, bits > T);
            const unsigned be = __ballot_sync(0xffffffffu, bits == T && i < PIX);
            gt += __popc(bg); eq += __popc(be);
        }
        if (lane == 0) { cgt[c] = gt; ceq[c] = eq; }
    }
    __syncthreads();
    if (tid == 0) {
        int sg = 0, se = 0;
        for (int c = 0; c < NCHK; c++) {
            const int tg2 = cgt[c], te = ceq[c];
            cgt[c] = sg; ceq[c] = se;
            sg += tg2; se += te;
        }
    }
    __syncthreads();

    const unsigned lmask = (1u << lane) - 1u;
    for (int c = wrp; c < NCHK; c += 32) {
        int gt_run = cgt[c], eq_run = ceq[c];
#pragma unroll
        for (int g = 0; g < 8; g++) {
            const int i = c * 256 + g * 32 + lane;
            const unsigned bits = (i < PIX) ? sbits[i] : 0u;
            const bool isgt = bits > T;
            const bool iseq = (bits == T) && (i < PIX);
            const unsigned bg = __ballot_sync(0xffffffffu, isgt);
            const unsigned be = __ballot_sync(0xffffffffu, iseq);
            const int gt_before = gt_run + __popc(bg & lmask);
            const int eq_before = eq_run + __popc(be & lmask);
            int slot = -1;
            if (isgt)                         slot = gt_before + min(eq_before, tn);
            else if (iseq && eq_before < tn)  slot = gt_before + eq_before;
            if (slot >= 0) {
                g_idx[b * KTOK + slot] = i;
                g_inv[b * PIX + i] = slot;
            }
            gt_run += __popc(bg);
            eq_run += __popc(be);
        }
    }
}

// ---------------------------------------------------------------------------
// 4) positional-encoding frequency table
// ---------------------------------------------------------------------------
__global__ void freq_kernel()
{
    const int i = threadIdx.x;           // 64
    const float cst = (float)(-(log(10000.0) / 128.0));
    const float a = (float)(2 * i) * cst;
    g_freq[i] = (float)exp((double)a);
}

// ---------------------------------------------------------------------------
// 5) gather tokens: tokens[b,k,c] = x[b,c,p]*imp[b,p] + PE[p,c]
//    (2 tokens per 256-thread block)
// ---------------------------------------------------------------------------
__global__ void gather_kernel(const float* __restrict__ x)
{
    const int b = blockIdx.y;
    const int k = blockIdx.x * 2 + (threadIdx.x >> 7);
    const int c = threadIdx.x & 127;
    const int p = g_idx[b * KTOK + k];
    const float val = x[((size_t)b * CCH + c) * PIX + p] * g_imp[b * PIX + p];
    const float arg = (float)p * g_freq[c >> 1];
    const float pe  = (c & 1) ? cosf(arg) : sinf(arg);
    g_tokens[((size_t)b * KTOK + k) * CCH + c] = val + pe;
}

// ---------------------------------------------------------------------------
// 6) unified tf32 tensor-core GEMM, BM=BN=128, 256 threads (4m x 2n warps).
//    out = act( A @ B^T + bias )            (DO_LN = false)
//    out = LN( A @ B^T + bias + R ) * g + b (DO_LN = true, N must be 128)
//    Per-output K-accumulation order identical to prior kernels.
// ---------------------------------------------------------------------------
template <bool RELU, bool DO_LN>
__global__ __launch_bounds__(256) void gemm_big(
    const float* __restrict__ A, const float* __restrict__ B,
    const float* __restrict__ bias, const float* __restrict__ R,
    const float* __restrict__ gam, const float* __restrict__ bet,
    float* __restrict__ out, int N, int K)
{
    __shared__ unsigned As[128][33];
    __shared__ unsigned Bs[128][33];
    __shared__ float2 part[2][128];

    const int tid  = threadIdx.x;
    const int lane = tid & 31;
    const int wid  = tid >> 5;
    const int wm   = wid >> 1;           // 0..3
    const int wn   = wid & 1;            // 0..1 (64-col halves)
    const int g    = lane >> 2;
    const int tg   = lane & 3;
    const int bm   = blockIdx.x * 128;
    const int bn   = blockIdx.y * 128;

    float acc[2][8][4];
#pragma unroll
    for (int mi = 0; mi < 2; mi++)
#pragma unroll
        for (int ni = 0; ni < 8; ni++)
#pragma unroll
            for (int e = 0; e < 4; e++) acc[mi][ni][e] = 0.f;

    for (int k0 = 0; k0 < K; k0 += 32) {
#pragma unroll
        for (int i = 0; i < 4; i++) {
            const int f = tid + i * 256;
            const int row = f >> 3, c4 = (f & 7) * 4;
            const float4 va = *(const float4*)&A[(size_t)(bm + row) * K + k0 + c4];
            As[row][c4 + 0] = tf32_of(va.x); As[row][c4 + 1] = tf32_of(va.y);
            As[row][c4 + 2] = tf32_of(va.z); As[row][c4 + 3] = tf32_of(va.w);
            const float4 vb = *(const float4*)&B[(size_t)(bn + row) * K + k0 + c4];
            Bs[row][c4 + 0] = tf32_of(vb.x); Bs[row][c4 + 1] = tf32_of(vb.y);
            Bs[row][c4 + 2] = tf32_of(vb.z); Bs[row][c4 + 3] = tf32_of(vb.w);
        }
        __syncthreads();

#pragma unroll
        for (int ks = 0; ks < 4; ks++) {
            const int kb = ks * 8;
            unsigned a[2][4], bf[8][2];
#pragma unroll
            for (int mi = 0; mi < 2; mi++) {
                const int r0 = wm * 32 + mi * 16 + g;
                a[mi][0] = As[r0][kb + tg];
                a[mi][1] = As[r0 + 8][kb + tg];
                a[mi][2] = As[r0][kb + tg + 4];
                a[mi][3] = As[r0 + 8][kb + tg + 4];
            }
#pragma unroll
            for (int ni = 0; ni < 8; ni++) {
                const int n0 = wn * 64 + ni * 8 + g;
                bf[ni][0] = Bs[n0][kb + tg];
                bf[ni][1] = Bs[n0][kb + tg + 4];
            }
#pragma unroll
            for (int mi = 0; mi < 2; mi++)
#pragma unroll
                for (int ni = 0; ni < 8; ni++)
                    mma_tf32(acc[mi][ni], a[mi], bf[ni]);
        }
        __syncthreads();
    }

    if (!DO_LN) {
        // plain epilogue: bias (+relu), direct store
#pragma unroll
        for (int mi = 0; mi < 2; mi++) {
            const int r0 = bm + wm * 32 + mi * 16 + g;
#pragma unroll
            for (int ni = 0; ni < 8; ni++) {
                const int c0 = bn + wn * 64 + ni * 8 + tg * 2;
                const float b0 = bias[c0], b1 = bias[c0 + 1];
                float2 v0 = { acc[mi][ni][0] + b0, acc[mi][ni][1] + b1 };
                float2 v1 = { acc[mi][ni][2] + b0, acc[mi][ni][3] + b1 };
                if (RELU) {
                    v0.x = fmaxf(v0.x, 0.f); v0.y = fmaxf(v0.y, 0.f);
                    v1.x = fmaxf(v1.x, 0.f); v1.y = fmaxf(v1.y, 0.f);
                }
                *(float2*)&out[(size_t)r0 * N + c0]       = v0;
                *(float2*)&out[(size_t)(r0 + 8) * N + c0] = v1;
            }
        }
        return;
    }

    // LN epilogue (N == 128, bn == 0)
    float v0s[2][8][2], v1s[2][8][2];
    float sum[2][2], sq[2][2];
#pragma unroll
    for (int mi = 0; mi < 2; mi++) {
        sum[mi][0] = sum[mi][1] = 0.f;
        sq[mi][0]  = sq[mi][1]  = 0.f;
        const int r0 = bm + wm * 32 + mi * 16 + g;
#pragma unroll
        for (int ni = 0; ni < 8; ni++) {
            const int c0 = wn * 64 + ni * 8 + tg * 2;
            const float b0 = bias[c0], b1 = bias[c0 + 1];
            const float2 ra = *(const float2*)&R[(size_t)r0 * CCH + c0];
            const float2 rb = *(const float2*)&R[(size_t)(r0 + 8) * CCH + c0];
            const float x0 = acc[mi][ni][0] + b0 + ra.x;
            const float x1 = acc[mi][ni][1] + b1 + ra.y;
            const float x2 = acc[mi][ni][2] + b0 + rb.x;
            const float x3 = acc[mi][ni][3] + b1 + rb.y;
            v0s[mi][ni][0] = x0; v0s[mi][ni][1] = x1;
            v1s[mi][ni][0] = x2; v1s[mi][ni][1] = x3;
            sum[mi][0] += x0 + x1;         sq[mi][0] += x0*x0 + x1*x1;
            sum[mi][1] += x2 + x3;         sq[mi][1] += x2*x2 + x3*x3;
        }
#pragma unroll
        for (int off = 1; off < 4; off <<= 1) {
            sum[mi][0] += __shfl_xor_sync(0xffffffffu, sum[mi][0], off);
            sq[mi][0]  += __shfl_xor_sync(0xffffffffu, sq[mi][0],  off);
            sum[mi][1] += __shfl_xor_sync(0xffffffffu, sum[mi][1], off);
            sq[mi][1]  += __shfl_xor_sync(0xffffffffu, sq[mi][1],  off);
        }
    }
    if (tg == 0) {
#pragma unroll
        for (int mi = 0; mi < 2; mi++) {
            const int rl = wm * 32 + mi * 16 + g;
            part[wn][rl]     = make_float2(sum[mi][0], sq[mi][0]);
            part[wn][rl + 8] = make_float2(sum[mi][1], sq[mi][1]);
        }
    }
    __syncthreads();

#pragma unroll
    for (int mi = 0; mi < 2; mi++) {
        const int rl = wm * 32 + mi * 16 + g;
#pragma unroll
        for (int half = 0; half < 2; half++) {
            const float2 p0 = part[0][rl + half * 8];
            const float2 p1 = part[1][rl + half * 8];
            const float mu  = (p0.x + p1.x) * (1.f / 128.f);
            const float var = (p0.y + p1.y) * (1.f / 128.f) - mu * mu;
            const float inv = rsqrtf(var + 1e-5f);
            const int row = bm + wm * 32 + mi * 16 + half * 8 + g;
#pragma unroll
            for (int ni = 0; ni < 8; ni++) {
                const int c0 = wn * 64 + ni * 8 + tg * 2;
                const float gv0 = gam[c0], gv1 = gam[c0 + 1];
                const float bv0 = bet[c0], bv1 = bet[c0 + 1];
                const float x0 = (half == 0) ? v0s[mi][ni][0] : v1s[mi][ni][0];
                const float x1 = (half == 0) ? v0s[mi][ni][1] : v1s[mi][ni][1];
                float2 o;
                o.x = (x0 - mu) * inv * gv0 + bv0;
                o.y = (x1 - mu) * inv * gv1 + bv1;
                *(float2*)&out[(size_t)row * CCH + c0] = o;
            }
        }
    }
}

// ---------------------------------------------------------------------------
// 7) tensor-core flash attention. grid (NHEAD, BATCH, 2), 256 threads.
// ---------------------------------------------------------------------------
__global__ __launch_bounds__(256) void attn_kernel()
{
    __shared__ unsigned sK[256][18];
    __shared__ unsigned sV[256][24];

    const int h = blockIdx.x, b = blockIdx.y, qh = blockIdx.z;
    const int tid  = threadIdx.x;
    const int lane = tid & 31;
    const int w    = tid >> 5;
    const int g    = lane >> 2;
    const int tg   = lane & 3;
    const float* qkv = g_qkv + (size_t)b * KTOK * 384;
    const int qbase = qh * 384 + w * 48;

    unsigned qa[3][8];
#pragma unroll
    for (int qt = 0; qt < 3; qt++) {
        const int row = qbase + qt * 16 + g;
        const float* q0 = qkv + (size_t)row * 384 + h * 16;
        const float* q8 = q0 + 8 * 384;
        qa[qt][0] = tf32_of(q0[tg]      * 0.25f);
        qa[qt][1] = tf32_of(q8[tg]      * 0.25f);
        qa[qt][2] = tf32_of(q0[tg + 4]  * 0.25f);
        qa[qt][3] = tf32_of(q8[tg + 4]  * 0.25f);
        qa[qt][4] = tf32_of(q0[tg + 8]  * 0.25f);
        qa[qt][5] = tf32_of(q8[tg + 8]  * 0.25f);
        qa[qt][6] = tf32_of(q0[tg + 12] * 0.25f);
        qa[qt][7] = tf32_of(q8[tg + 12] * 0.25f);
    }

    float m[3][2], l[3][2], o[3][2][4];
#pragma unroll
    for (int qt = 0; qt < 3; qt++) {
        m[qt][0] = m[qt][1] = -1e30f;
        l[qt][0] = l[qt][1] = 0.f;
#pragma unroll
        for (int n = 0; n < 2; n++)
#pragma unroll
            for (int e = 0; e < 4; e++) o[qt][n][e] = 0.f;
    }

    const int src0 = (lane & 28) | (tg >> 1);
    const int src2 = src0 + 2;

    for (int ch = 0; ch < 3; ch++) {
        __syncthreads();
        for (int e = tid; e < 256 * 16; e += 256) {
            const int j = e >> 4, d = e & 15;
            const size_t base = (size_t)(ch * 256 + j) * 384 + h * 16 + d;
            sK[j][d] = tf32_of(qkv[base + 128]);
            sV[j][d] = tf32_of(qkv[base + 256]);
        }
        __syncthreads();

        for (int sub = 0; sub < 8; sub++) {
            unsigned kb[4][2][2];
#pragma unroll
            for (int t = 0; t < 4; t++) {
                const int key = sub * 32 + t * 8 + g;
                kb[t][0][0] = sK[key][tg];
                kb[t][0][1] = sK[key][tg + 4];
                kb[t][1][0] = sK[key][tg + 8];
                kb[t][1][1] = sK[key][tg + 12];
            }
#pragma unroll
            for (int qt = 0; qt < 3; qt++) {
                float s[4][4];
#pragma unroll
                for (int t = 0; t < 4; t++) {
                    s[t][0] = s[t][1] = s[t][2] = s[t][3] = 0.f;
                    mma_tf32(s[t], qa[qt],     kb[t][0]);
                    mma_tf32(s[t], qa[qt] + 4, kb[t][1]);
                }
                float mx0 = s[0][0], mx1 = s[0][2];
#pragma unroll
                for (int t = 0; t < 4; t++) {
                    mx0 = fmaxf(mx0, fmaxf(s[t][0], s[t][1]));
                    mx1 = fmaxf(mx1, fmaxf(s[t][2], s[t][3]));
                }
                mx0 = fmaxf(mx0, __shfl_xor_sync(0xffffffffu, mx0, 1));
                mx0 = fmaxf(mx0, __shfl_xor_sync(0xffffffffu, mx0, 2));
                mx1 = fmaxf(mx1, __shfl_xor_sync(0xffffffffu, mx1, 1));
                mx1 = fmaxf(mx1, __shfl_xor_sync(0xffffffffu, mx1, 2));
                const float nm0 = fmaxf(m[qt][0], mx0);
                const float nm1 = fmaxf(m[qt][1], mx1);
                const float f0 = __expf(m[qt][0] - nm0);
                const float f1 = __expf(m[qt][1] - nm1);
                m[qt][0] = nm0; m[qt][1] = nm1;
                float s0 = 0.f, s1 = 0.f;
#pragma unroll
                for (int t = 0; t < 4; t++) {
                    s[t][0] = tf32f(__expf(s[t][0] - nm0));
                    s[t][1] = tf32f(__expf(s[t][1] - nm0));
                    s[t][2] = tf32f(__expf(s[t][2] - nm1));
                    s[t][3] = tf32f(__expf(s[t][3] - nm1));
                    s0 += s[t][0] + s[t][1];
                    s1 += s[t][2] + s[t][3];
                }
                l[qt][0] = l[qt][0] * f0 + s0;
                l[qt][1] = l[qt][1] * f1 + s1;
#pragma unroll
                for (int n = 0; n < 2; n++) {
                    o[qt][n][0] *= f0; o[qt][n][1] *= f0;
                    o[qt][n][2] *= f1; o[qt][n][3] *= f1;
                }
#pragma unroll
                for (int t = 0; t < 4; t++) {
                    unsigned a[4];
                    {
                        const float t00 = __shfl_sync(0xffffffffu, s[t][0], src0);
                        const float t01 = __shfl_sync(0xffffffffu, s[t][1], src0);
                        const float t10 = __shfl_sync(0xffffffffu, s[t][2], src0);
                        const float t11 = __shfl_sync(0xffffffffu, s[t][3], src0);
                        a[0] = __float_as_uint((tg & 1) ? t01 : t00);
                        a[1] = __float_as_uint((tg & 1) ? t11 : t10);
                        const float u00 = __shfl_sync(0xffffffffu, s[t][0], src2);
                        const float u01 = __shfl_sync(0xffffffffu, s[t][1], src2);
                        const float u10 = __shfl_sync(0xffffffffu, s[t][2], src2);
                        const float u11 = __shfl_sync(0xffffffffu, s[t][3], src2);
                        a[2] = __float_as_uint((tg & 1) ? u01 : u00);
                        a[3] = __float_as_uint((tg & 1) ? u11 : u10);
                    }
                    const int key = sub * 32 + t * 8;
                    unsigned vb0[2], vb1[2];
                    vb0[0] = sV[key + tg][g];         vb0[1] = sV[key + tg + 4][g];
                    vb1[0] = sV[key + tg][g + 8];     vb1[1] = sV[key + tg + 4][g + 8];
                    mma_tf32(o[qt][0], a, vb0);
                    mma_tf32(o[qt][1], a, vb1);
                }
            }
        }
    }

#pragma unroll
    for (int qt = 0; qt < 3; qt++) {
        float l0 = l[qt][0], l1 = l[qt][1];
        l0 += __shfl_xor_sync(0xffffffffu, l0, 1);
        l0 += __shfl_xor_sync(0xffffffffu, l0, 2);
        l1 += __shfl_xor_sync(0xffffffffu, l1, 1);
        l1 += __shfl_xor_sync(0xffffffffu, l1, 2);
        const float inv0 = 1.f / l0, inv1 = 1.f / l1;
        const int row = qbase + qt * 16 + g;
        float* out0 = g_attn + ((size_t)b * KTOK + row) * CCH + h * 16 + tg * 2;
        float* out8 = out0 + 8 * CCH;
#pragma unroll
        for (int n = 0; n < 2; n++) {
            *(float2*)(out0 + n * 8) = make_float2(o[qt][n][0] * inv0, o[qt][n][1] * inv0);
            *(float2*)(out8 + n * 8) = make_float2(o[qt][n][2] * inv1, o[qt][n][3] * inv1);
        }
    }
}

// ---------------------------------------------------------------------------
// 9) finalize: out = x*imp everywhere, except selected pixels take t2.
// ---------------------------------------------------------------------------
__global__ void finalize_kernel(const float* __restrict__ x, float* __restrict__ out)
{
    const unsigned i = blockIdx.x * 256u + threadIdx.x;
    const unsigned total = (unsigned)BATCH * CCH * (PIX / 4);
    if (i >= total) return;
    const unsigned base = i * 4u;
    const unsigned p4 = base % PIX;
    const unsigned bc = base / PIX;
    const unsigned b  = bc / CCH;
    const unsigned c  = bc - b * CCH;
    const float4 xv = *(const float4*)(x + base);
    const float* ip = g_imp + (size_t)b * PIX + p4;
    const int4  iv = *(const int4*)(g_inv + (size_t)b * PIX + p4);
    float4 o;
    o.x = (iv.x >= 0) ? g_t2[((size_t)b * KTOK + iv.x) * CCH + c] : xv.x * ip[0];
    o.y = (iv.y >= 0) ? g_t2[((size_t)b * KTOK + iv.y) * CCH + c] : xv.y * ip[1];
    o.z = (iv.z >= 0) ? g_t2[((size_t)b * KTOK + iv.z) * CCH + c] : xv.z * ip[2];
    o.w = (iv.w >= 0) ? g_t2[((size_t)b * KTOK + iv.w) * CCH + c] : xv.w * ip[3];
    *(float4*)(out + base) = o;
}

// ---------------------------------------------------------------------------
// launch (R8 structure; unified BN=128 GEMMs)
// ---------------------------------------------------------------------------
extern "C" void kernel_launch(void* const* d_in, const int* in_sizes, int n_in,
                              void* d_out, int out_size)
{
    const float* x      = (const float*)d_in[0];
    const float* conv_w = (const float*)d_in[1];
    const float* conv_b = (const float*)d_in[2];
    const float* bn_g   = (const float*)d_in[3];
    const float* bn_b   = (const float*)d_in[4];
    const float* bn_m   = (const float*)d_in[5];
    const float* bn_v   = (const float*)d_in[6];
    const float* w_qkv  = (const float*)d_in[7];
    const float* b_qkv  = (const float*)d_in[8];
    const float* w_o    = (const float*)d_in[9];
    const float* b_o    = (const float*)d_in[10];
    const float* ln1_g  = (const float*)d_in[11];
    const float* ln1_b  = (const float*)d_in[12];
    const float* w1     = (const float*)d_in[13];
    const float* b1     = (const float*)d_in[14];
    const float* w2     = (const float*)d_in[15];
    const float* b2     = (const float*)d_in[16];
    const float* ln2_g  = (const float*)d_in[17];
    const float* ln2_b  = (const float*)d_in[18];
    float* out = (float*)d_out;

    float *p_tokens, *p_qkv, *p_attn, *p_t1, *p_h1, *p_t2;
    cudaGetSymbolAddress((void**)&p_tokens, g_tokens);
    cudaGetSymbolAddress((void**)&p_qkv,    g_qkv);
    cudaGetSymbolAddress((void**)&p_attn,   g_attn);
    cudaGetSymbolAddress((void**)&p_t1,     g_t1);
    cudaGetSymbolAddress((void**)&p_h1,     g_h1);
    cudaGetSymbolAddress((void**)&p_t2,     g_t2);

    const int convgemm_smem = (2 * 64 * 132 + 2 * 32 * 132) * (int)sizeof(unsigned);
    cudaFuncSetAttribute(convgemm_kernel, cudaFuncAttributeMaxDynamicSharedMemorySize,
                         convgemm_smem);
    cudaFuncSetAttribute(topk_kernel, cudaFuncAttributeMaxDynamicSharedMemorySize,
                         PIX * (int)sizeof(unsigned));

    // conv -> importance -> top-K (+inverse map) -> tokens
    freq_kernel<<<1, 64>>>();
    convgemm_kernel<<<dim3(NPT, BATCH), 256, convgemm_smem>>>(x, conv_w);
    convadd_kernel<<<(BATCH * PIX + 255) / 256, 256>>>(conv_b, bn_g, bn_b, bn_m, bn_v);
    topk_kernel<<<BATCH, TKT, PIX * sizeof(unsigned)>>>();
    gather_kernel<<<dim3(KTOK / 2, BATCH), 256>>>(x);

    // transformer encoder layer (tf32 tensor cores, unified 128x128 tiles)
    gemm_big<false, false><<<dim3(NTOK / 128, 384 / 128), 256>>>(
        p_tokens, w_qkv, b_qkv, nullptr, nullptr, nullptr, p_qkv, 384, 128);
    attn_kernel<<<dim3(NHEAD, BATCH, 2), 256>>>();
    gemm_big<false, true><<<dim3(NTOK / 128, 1), 256>>>(
        p_attn, w_o, b_o, p_tokens, ln1_g, ln1_b, p_t1, 128, 128);
    gemm_big<true, false><<<dim3(NTOK / 128, 256 / 128), 256>>>(
        p_t1, w1, b1, nullptr, nullptr, nullptr, p_h1, 256, 128);
    gemm_big<false, true><<<dim3(NTOK / 128, 1), 256>>>(
        p_h1, w2, b2, p_t1, ln2_g, ln2_b, p_t2, 128, 256);

    // assemble output in one pass
    finalize_kernel<<<(BATCH * CCH * (PIX / 4) + 255) / 256, 256>>>(x, out);
}